// round 15
// baseline (speedup 1.0000x reference)
#include <cuda_runtime.h>
#include <cuda_fp16.h>
#include <cstdint>

// Problem constants
#define TT 2048
#define EE 768

// ---------------- scratch (device global, zero-init .bss) ----------------
static constexpr long OFF_WE    = 0;
static constexpr long OFF_G     = OFF_WE    + 2048L * 768;
static constexpr long OFF_MH1   = OFF_G     + 256L * 2304;
static constexpr long OFF_M     = OFF_MH1   + 256L * 160;
static constexpr long OFF_HI    = OFF_M     + 256L;
static constexpr long OFF_HJB   = OFF_HI    + 256L * 160;
static constexpr long OFF_H1P   = OFF_HJB   + 256L * 160;
static constexpr long SCRATCH_TOTAL = OFF_H1P + 65536L * 160;
// split-K partial buffers alias the h1p region (consumed before pair_h1)
static constexpr long OFF_PART  = OFF_H1P;

__device__ __align__(16) float g_scratch[SCRATCH_TOTAL];

// Wc transposed, f16: [160 n][2304 k]
__device__ __align__(16) unsigned short g_wct[160L * 2304];
// W2 transposed, f16: [160 n][160 k]
__device__ __align__(16) unsigned short g_w2t[160L * 160];

// ======================= helpers ==========================
__device__ __forceinline__ uint32_t smem_u32(const void* p) {
    uint32_t a;
    asm("{ .reg .u64 t; cvta.to.shared.u64 t, %1; cvt.u32.u64 %0, t; }"
        : "=r"(a) : "l"(p));
    return a;
}
#define SWZ(x) ((x) ^ (((x) >> 3) & 0x70))
#define STS128(a0, a1, a2, a3, addr) \
    asm volatile("st.shared.v4.b32 [%0], {%1,%2,%3,%4};" \
                 :: "r"(addr), "r"(a0), "r"(a1), "r"(a2), "r"(a3) : "memory")

__device__ __forceinline__ uint32_t pack_h2(float lo, float hi) {
    uint32_t d;
    asm("cvt.rn.f16x2.f32 %0, %1, %2;" : "=r"(d) : "f"(hi), "f"(lo));
    return d;
}

#define LDSM_X4(r0, r1, r2, r3, a) \
    asm volatile("ldmatrix.sync.aligned.m8n8.x4.shared.b16 {%0,%1,%2,%3}, [%4];" \
                 : "=r"(r0), "=r"(r1), "=r"(r2), "=r"(r3) : "r"(a))
#define LDSM_X2(r0, r1, a) \
    asm volatile("ldmatrix.sync.aligned.m8n8.x2.shared.b16 {%0,%1}, [%2];" \
                 : "=r"(r0), "=r"(r1) : "r"(a))
#define MMAF16(c, A0, A1, A2, A3, B0, B1) \
    asm volatile("mma.sync.aligned.m16n8k16.row.col.f32.f16.f16.f32 " \
                 "{%0,%1,%2,%3}, {%4,%5,%6,%7}, {%8,%9}, {%0,%1,%2,%3};" \
                 : "+f"((c)[0]), "+f"((c)[1]), "+f"((c)[2]), "+f"((c)[3]) \
                 : "r"(A0), "r"(A1), "r"(A2), "r"(A3), "r"(B0), "r"(B1))

// ---------------- weight prep: Wc^T f16 + W2^T f16 ----------------------
__global__ __launch_bounds__(256) void prep_weights(
    const float* __restrict__ Wc, const float* __restrict__ W2)
{
    long idx = (long)blockIdx.x * 256 + threadIdx.x;
    int n = (int)(idx / 2304);
    int k = (int)(idx - (long)n * 2304);
    float w = (n < 150) ? Wc[(long)k * 150 + n] : 0.f;
    g_wct[idx] = __half_as_ushort(__float2half_rn(w));
    if (idx < 160 * 160) {
        int n2 = (int)(idx / 160), k2 = (int)(idx - (long)n2 * 160);
        float w2 = (n2 < 150 && k2 < 150) ? W2[(long)k2 * 150 + n2] : 0.f;
        g_w2t[idx] = __half_as_ushort(__float2half_rn(w2));
    }
}

// ---------------- split-K GEMM: partials, no bias/act -------------------
__global__ __launch_bounds__(256) void gemm_split(
    const float* __restrict__ Aext, long aOff, int lda,
    const float* __restrict__ W0, const float* __restrict__ W1,
    const float* __restrict__ W2,
    long partOff, int Mtot, int kPerSplit)
{
    const float* A = Aext ? Aext : (g_scratch + aOff);
    const float* W = (blockIdx.z == 0) ? W0 : ((blockIdx.z == 1) ? W1 : W2);
    float* P = g_scratch + partOff
             + ((long)(blockIdx.z * gridDim.y + blockIdx.y) * Mtot) * 160;

    __shared__ float sA[16][68];
    __shared__ float sW[16][160];

    int tid = threadIdx.x;
    int rg = tid >> 4;
    int cg = tid & 15;
    int row0 = blockIdx.x * 64;
    int kbase = blockIdx.y * kPerSplit;

    float acc[4][10];
#pragma unroll
    for (int a = 0; a < 4; a++)
#pragma unroll
        for (int b = 0; b < 10; b++) acc[a][b] = 0.f;

    int nCh = kPerSplit >> 4;
    for (int ch = 0; ch < nCh; ch++) {
        int k0 = kbase + ch * 16;
        {
            int c = tid & 15, r = tid >> 4;
#pragma unroll
            for (int pass = 0; pass < 4; pass++) {
                int rl = pass * 16 + r;
                sA[c][rl] = A[(long)(row0 + rl) * lda + k0 + c];
            }
        }
#pragma unroll
        for (int i = 0; i < 10; i++) {
            int idx = tid + i * 256;
            int k = idx / 160, h = idx - k * 160;
            sW[k][h] = (h < 150) ? W[(long)(k0 + k) * 150 + h] : 0.f;
        }
        __syncthreads();
#pragma unroll
        for (int k = 0; k < 16; k++) {
            float4 a4 = *(const float4*)&sA[k][rg * 4];
            float av0 = a4.x, av1 = a4.y, av2 = a4.z, av3 = a4.w;
#pragma unroll
            for (int hh = 0; hh < 10; hh += 2) {
                float2 w = *(const float2*)&sW[k][cg * 10 + hh];
                acc[0][hh]     += av0 * w.x;  acc[0][hh + 1] += av0 * w.y;
                acc[1][hh]     += av1 * w.x;  acc[1][hh + 1] += av1 * w.y;
                acc[2][hh]     += av2 * w.x;  acc[2][hh + 1] += av2 * w.y;
                acc[3][hh]     += av3 * w.x;  acc[3][hh + 1] += av3 * w.y;
            }
        }
        __syncthreads();
    }

#pragma unroll
    for (int rr = 0; rr < 4; rr++) {
        int row = row0 + rg * 4 + rr;
#pragma unroll
        for (int hh = 0; hh < 10; hh++) {
            int h = cg * 10 + hh;
            if (h < 150) P[(long)row * 160 + h] = acc[rr][hh];
        }
    }
}

// ------- fused: token L1-reduce + L2 + attn dot + we = e*attn -----------
// Whole aW2 staged in smem once (no chunk serialization). 16 tokens/CTA.
#define TOK2_SW 0                    // [150][160] f32 = 96000 B
#define TOK2_SA 96000                // [16][160]  f32 = 10240 B
#define TOK2_SMEM (96000 + 10240)

__global__ __launch_bounds__(256) void tok2_attn_we_kernel(
    const float* __restrict__ ab1,
    const float* __restrict__ W,  const float* __restrict__ b2,
    const float* __restrict__ w3, const float* __restrict__ b3,
    const float* __restrict__ e)
{
    extern __shared__ __align__(16) char smem[];
    float* sW = (float*)(smem + TOK2_SW);
    float* sA = (float*)(smem + TOK2_SA);
    __shared__ float sRed[16][16];
    __shared__ float sAttn[16];

    const float* part = g_scratch + OFF_PART;
    float* we = g_scratch + OFF_WE;

    int tid = threadIdx.x;
    int rg = tid >> 4;
    int cg = tid & 15;
    int row0 = blockIdx.x * 16;

    // load full W tile: 150 x 160 (h >= 150 zero)
    for (int t = 0; t < 94; t++) {
        int idx = tid + t * 256;
        if (idx < 24000) {
            int k = idx / 160, h = idx - k * 160;
            sW[idx] = (h < 150) ? W[(long)k * 150 + h] : 0.f;
        }
    }
    // load A tile: 16 tokens x 160 (relu(sum 6 partials + ab1), k-major)
#pragma unroll
    for (int t = 0; t < 10; t++) {
        int idx = tid + t * 256;
        int r = idx / 160, c = idx - r * 160;
        float v = 0.f;
        if (c < 150) {
            long off = ((long)(row0 + r)) * 160 + c;
            float s = 0.f;
#pragma unroll
            for (int p = 0; p < 6; p++)
                s += part[(long)p * 2048 * 160 + off];
            v = fmaxf(s + ab1[c], 0.f);
        }
        sA[idx] = v;
    }
    __syncthreads();

    // straight-line GEMM: token rg, outputs cg*10..cg*10+9, k = 0..149
    float acc[10];
#pragma unroll
    for (int b = 0; b < 10; b++) acc[b] = 0.f;
    const float* sArow = sA + rg * 160;
#pragma unroll 2
    for (int k = 0; k < 150; k++) {
        float a = sArow[k];
        const float2* w2 = (const float2*)(sW + k * 160 + cg * 10);
#pragma unroll
        for (int hh = 0; hh < 5; hh++) {
            float2 w = w2[hh];
            acc[hh * 2]     += a * w.x;
            acc[hh * 2 + 1] += a * w.y;
        }
    }

    float partd = 0.f;
#pragma unroll
    for (int hh = 0; hh < 10; hh++) {
        int h = cg * 10 + hh;
        if (h < 150) partd += fmaxf(acc[hh] + b2[h], 0.f) * w3[h];
    }
    sRed[rg][cg] = partd;
    __syncthreads();
    if (tid < 16) {
        float s = b3[0];
#pragma unroll
        for (int c = 0; c < 16; c++) s += sRed[tid][c];
        sAttn[tid] = s;
    }
    __syncthreads();
#pragma unroll
    for (int it = 0; it < 48; it++) {
        int lin = it * 256 + tid;
        int r = lin / 768, c = lin - r * 768;
        long t = row0 + r;
        we[t * 768 + c] = e[t * 768 + c] * sAttn[r];
    }
}

// ---------------- m tail: m = relu(mh1@mW2+mb2).mW3 + mb3 ---------------
__global__ __launch_bounds__(256) void mtail_kernel(
    const float* __restrict__ W,  const float* __restrict__ b2,
    const float* __restrict__ w3, const float* __restrict__ b3)
{
    const float* A = g_scratch + OFF_MH1;
    float* mo = g_scratch + OFF_M;

    __shared__ float sA[16][20];
    __shared__ float sW[16][160];
    __shared__ float sRed[16][16];

    int tid = threadIdx.x;
    int rg = tid >> 4;
    int cg = tid & 15;
    int row0 = blockIdx.x * 16;

    float acc[10];
#pragma unroll
    for (int b = 0; b < 10; b++) acc[b] = 0.f;

    for (int ch = 0; ch < 10; ch++) {
        int k0 = ch * 16;
        {
            int c = tid & 15, r = tid >> 4;
            float v = 0.f;
            if (k0 + c < 150) v = A[(long)(row0 + r) * 160 + k0 + c];
            sA[c][r] = v;
        }
#pragma unroll
        for (int i = 0; i < 10; i++) {
            int idx = tid + i * 256;
            int k = idx / 160, h = idx - k * 160;
            float v = 0.f;
            if (k0 + k < 150 && h < 150) v = W[(long)(k0 + k) * 150 + h];
            sW[k][h] = v;
        }
        __syncthreads();
#pragma unroll
        for (int k = 0; k < 16; k++) {
            float av = sA[k][rg];
#pragma unroll
            for (int hh = 0; hh < 10; hh += 2) {
                float2 w = *(const float2*)&sW[k][cg * 10 + hh];
                acc[hh]     += av * w.x;
                acc[hh + 1] += av * w.y;
            }
        }
        __syncthreads();
    }

    float partd = 0.f;
#pragma unroll
    for (int hh = 0; hh < 10; hh++) {
        int h = cg * 10 + hh;
        if (h < 150) partd += fmaxf(acc[hh] + b2[h], 0.f) * w3[h];
    }
    sRed[rg][cg] = partd;
    __syncthreads();
    if (tid < 16) {
        float s = b3[0];
#pragma unroll
        for (int c = 0; c < 16; c++) s += sRed[tid][c];
        mo[row0 + tid] = s;
    }
}

// ---------------- 3-way reduce: mh1 / hi / hjb --------------------------
__global__ __launch_bounds__(160) void reduce_3(
    const float* __restrict__ mb1, const float* __restrict__ pb1)
{
    int row = blockIdx.x, z = blockIdx.y, c = threadIdx.x;
    float s = 0.f;
    if (c < 150) {
#pragma unroll
        for (int k = 0; k < 12; k++)
            s += g_scratch[OFF_PART + ((long)(z * 12 + k) * 256 + row) * 160 + c];
    }
    if (z == 0) {
        float v = (c < 150) ? fmaxf(s + mb1[c], 0.f) : 0.f;
        g_scratch[OFF_MH1 + (long)row * 160 + c] = v;
    } else if (z == 1) {
        g_scratch[OFF_HI + (long)row * 160 + c] = s;
    } else {
        float v = s + ((c < 150) ? pb1[c] : 0.f);
        g_scratch[OFF_HJB + (long)row * 160 + c] = v;
    }
}

// ---------------- g = [e_start | e_end | span_sum], 768 thr/blk ---------
__global__ __launch_bounds__(768) void gather_g_kernel(
    const float* __restrict__ e,
    const int* __restrict__ sp, const int* __restrict__ wd)
{
    const float* we = g_scratch + OFF_WE;
    float* g = g_scratch + OFF_G;
    int s = blockIdx.x, c = threadIdx.x;
    int st = sp[s];
    int en = st + wd[s];
    if (en > TT - 1) en = TT - 1;
    if (en < 0) en = 0;
    g[(long)s * 2304 + c]        = e[(long)st * 768 + c];
    g[(long)s * 2304 + 768 + c]  = e[(long)en * 768 + c];
    float sum = 0.f;
    for (int t = st; t <= en; t++) sum += we[(long)t * 768 + c];
    g[(long)s * 2304 + 1536 + c] = sum;
}

// ================= pair_h1: lower-triangle hij, f16 f32-acc mma =========
// R12 structure: grid (64 jq, 4 ib), 4 j's per CTA, full K.
#define PH1_A  0
#define PH1_B  32768
#define PH1_BUF 53248
#define PH1_SMEM (2 * PH1_BUF)

__global__ void __launch_bounds__(512, 1) pair_h1_mma()
{
    extern __shared__ __align__(1024) char smem[];
    uint32_t sb = smem_u32(smem);

    const float* g = g_scratch + OFF_G;
    float* h1p     = g_scratch + OFF_H1P;

    int tid  = threadIdx.x;
    int lane = tid & 31;
    int wid  = tid >> 5;
    int jq   = blockIdx.x;
    int ib   = blockIdx.y;

    int j0 = jq * 4;
    int fj = j0 & ~15;
    int i0 = fj + ib * 64;
    if (i0 >= 256) return;
    int M = 256 - i0;
    if (M > 64) M = 64;

    int jsel = wid >> 2;
    int wn   = (wid & 3) * 40;

    float acc[4][5][4];
#pragma unroll
    for (int a = 0; a < 4; a++)
#pragma unroll
        for (int b = 0; b < 5; b++)
#pragma unroll
            for (int c = 0; c < 4; c++) acc[a][b][c] = 0.f;

    int arow = tid >> 3;
    int seg  = tid & 7;
    int gi_row = i0 + arow; if (gi_row > 255) gi_row = 255;
    const float* gi_base = g + (long)gi_row * 2304 + seg * 8;

    auto stage = [&](int ch) {
        uint32_t tb = sb + (uint32_t)(ch & 1) * PH1_BUF;
        int k0 = ch * 64;
        {
            const float4* gi4 = (const float4*)(gi_base + k0);
            float4 a0 = gi4[0], a1 = gi4[1];
            uint32_t sw = SWZ((uint32_t)(arow * 128 + seg * 16));
#pragma unroll
            for (int jj = 0; jj < 4; jj++) {
                const float4* gj4 =
                    (const float4*)(g + (long)(j0 + jj) * 2304 + seg * 8 + k0);
                float4 w0 = gj4[0], w1 = gj4[1];
                uint32_t h01 = pack_h2(a0.x * w0.x, a0.y * w0.y);
                uint32_t h23 = pack_h2(a0.z * w0.z, a0.w * w0.w);
                uint32_t h45 = pack_h2(a1.x * w1.x, a1.y * w1.y);
                uint32_t h67 = pack_h2(a1.z * w1.z, a1.w * w1.w);
                STS128(h01, h23, h45, h67,
                       tb + PH1_A + (uint32_t)jj * 8192 + sw);
            }
        }
#pragma unroll
        for (int t = 0; t < 3; t++) {
            int idx = tid + t * 512;
            if (idx < 1280) {
                int n = idx >> 3, u = idx & 7;
                uint4 v = *(const uint4*)(g_wct + (long)n * 2304 + k0 + u * 8);
                uint32_t sw = SWZ((uint32_t)(n * 128 + u * 16));
                STS128(v.x, v.y, v.z, v.w, tb + PH1_B + sw);
            }
        }
    };

    stage(0);
    __syncthreads();

    for (int ch = 0; ch < 36; ch++) {
        if (ch < 35) stage(ch + 1);
        uint32_t tb = sb + (uint32_t)(ch & 1) * PH1_BUF;
        uint32_t ta = tb + PH1_A + (uint32_t)jsel * 8192;
#pragma unroll
        for (int ks = 0; ks < 4; ks++) {
            uint32_t Bf[5][2];
            {
                int m = lane >> 3;
                int n = wn + (m >> 1) * 8 + (lane & 7);
                uint32_t off = SWZ((uint32_t)(n * 128 + ks * 32 + (m & 1) * 16));
                LDSM_X4(Bf[0][0], Bf[0][1], Bf[1][0], Bf[1][1], tb + PH1_B + off);
            }
            {
                int m = lane >> 3;
                int n = wn + 16 + (m >> 1) * 8 + (lane & 7);
                uint32_t off = SWZ((uint32_t)(n * 128 + ks * 32 + (m & 1) * 16));
                LDSM_X4(Bf[2][0], Bf[2][1], Bf[3][0], Bf[3][1], tb + PH1_B + off);
            }
            {
                int n = wn + 32 + (lane & 7);
                uint32_t off = SWZ((uint32_t)(n * 128 + ks * 32 + ((lane >> 3) & 1) * 16));
                LDSM_X2(Bf[4][0], Bf[4][1], tb + PH1_B + off);
            }
#pragma unroll
            for (int mt = 0; mt < 4; mt++) {
                if (mt * 16 >= M) continue;
                int r = mt * 16 + (lane & 15);
                uint32_t aoff = SWZ((uint32_t)(r * 128 + ks * 32 + (lane >> 4) * 16));
                uint32_t A0, A1, A2, A3;
                LDSM_X4(A0, A1, A2, A3, ta + aoff);
#pragma unroll
                for (int nt = 0; nt < 5; nt++)
                    MMAF16(acc[mt][nt], A0, A1, A2, A3, Bf[nt][0], Bf[nt][1]);
            }
        }
        __syncthreads();
    }

    {
        int j = j0 + jsel;
#pragma unroll
        for (int mt = 0; mt < 4; mt++) {
            if (mt * 16 >= M) continue;
#pragma unroll
            for (int nt = 0; nt < 5; nt++) {
                int c = wn + nt * 8 + (lane & 3) * 2;
#pragma unroll
                for (int h = 0; h < 2; h++) {
                    int i = i0 + mt * 16 + (lane >> 2) + h * 8;
                    *(float2*)(h1p + ((long)i * 256 + j) * 160 + c) =
                        make_float2(acc[mt][nt][h * 2], acc[mt][nt][h * 2 + 1]);
                }
            }
        }
    }
}

// ============ pair_out on tensor cores (64 pairs/CTA, f16) ==============
#define PO_A 0
#define PO_B 24576
#define PO_RED 86016
#define PO_SMEM (86016 + 64 * 4 * 4)

__global__ void __launch_bounds__(256, 2) pair_out_mma(
    const float* __restrict__ pb2, const float* __restrict__ w3,
    const float* __restrict__ pb3, float* __restrict__ out)
{
    extern __shared__ __align__(1024) char smem[];
    uint32_t sb = smem_u32(smem);
    float* sRed = (float*)(smem + PO_RED);     // [64][4]

    const float* h1p = g_scratch + OFF_H1P;
    const float* mm  = g_scratch + OFF_M;
    const float* hi  = g_scratch + OFF_HI;
    const float* hjb = g_scratch + OFF_HJB;

    int tid  = threadIdx.x;
    int lane = tid & 31;
    int wid  = tid >> 5;
    long p0 = (long)blockIdx.x * 64;
    int i_fix = (int)(p0 >> 8);
    int j0 = (int)(p0 & 255);

    int wm = (wid >> 2) * 32;
    int wn = (wid & 3) * 40;

    // ---- stage A: assemble h1 = relu(hij + hi + hjb), f16, swizzled ----
    {
        const float* hirow = hi + (long)i_fix * 160;
#pragma unroll
        for (int t = 0; t < 8; t++) {
            int idx = tid + t * 256;
            int p = idx >> 5, seg = idx & 31;
            if (seg < 20) {
                int j = j0 + p;
                long src = (j <= i_fix) ? ((long)i_fix * 256 + j)
                                        : ((long)j * 256 + i_fix);
                int kc = seg * 8;
                const float4* s4 = (const float4*)(h1p + src * 160 + kc);
                const float4* h4 = (const float4*)(hirow + kc);
                const float4* b4 = (const float4*)(hjb + (long)j * 160 + kc);
                float4 x0 = s4[0], x1 = s4[1];
                float4 y0 = h4[0], y1 = h4[1];
                float4 z0 = b4[0], z1 = b4[1];
                float f0 = fmaxf(x0.x + y0.x + z0.x, 0.f);
                float f1 = fmaxf(x0.y + y0.y + z0.y, 0.f);
                float f2 = fmaxf(x0.z + y0.z + z0.z, 0.f);
                float f3 = fmaxf(x0.w + y0.w + z0.w, 0.f);
                float f4 = fmaxf(x1.x + y1.x + z1.x, 0.f);
                float f5 = fmaxf(x1.y + y1.y + z1.y, 0.f);
                float f6 = fmaxf(x1.z + y1.z + z1.z, 0.f);
                float f7 = fmaxf(x1.w + y1.w + z1.w, 0.f);
                uint32_t h01 = pack_h2(f0, f1), h23 = pack_h2(f2, f3);
                uint32_t h45 = pack_h2(f4, f5), h67 = pack_h2(f6, f7);
                int kblk = seg >> 3, uu = seg & 7;
                uint32_t addr = sb + PO_A + (uint32_t)kblk * 8192
                              + SWZ((uint32_t)(p * 128 + uu * 16));
                STS128(h01, h23, h45, h67, addr);
            }
        }
    }
    // ---- stage B: W2^T f16 ----
    {
#pragma unroll
        for (int t = 0; t < 15; t++) {
            int idx = tid + t * 256;
            if (idx < 3840) {
                int n = idx / 24, u = idx - n * 24;
                int kblk = u >> 3, uu = u & 7;
                int k0 = kblk * 64 + uu * 8;
                uint4 v = make_uint4(0, 0, 0, 0);
                if (k0 < 160) v = *(const uint4*)(g_w2t + (long)n * 160 + k0);
                uint32_t addr = sb + PO_B + (uint32_t)kblk * 20480
                              + SWZ((uint32_t)(n * 128 + uu * 16));
                STS128(v.x, v.y, v.z, v.w, addr);
            }
        }
    }
    __syncthreads();

    float acc[2][5][4];
#pragma unroll
    for (int a = 0; a < 2; a++)
#pragma unroll
        for (int b = 0; b < 5; b++)
#pragma unroll
            for (int c = 0; c < 4; c++) acc[a][b][c] = 0.f;

#pragma unroll
    for (int kblk = 0; kblk < 3; kblk++) {
        uint32_t ta = sb + PO_A + (uint32_t)kblk * 8192;
        uint32_t tbb = sb + PO_B + (uint32_t)kblk * 20480;
        int kmax = (kblk == 2) ? 2 : 4;
#pragma unroll
        for (int ks = 0; ks < 4; ks++) {
            if (ks >= kmax) break;
            uint32_t Bf[5][2];
            {
                int m = lane >> 3;
                int n = wn + (m >> 1) * 8 + (lane & 7);
                uint32_t off = SWZ((uint32_t)(n * 128 + ks * 32 + (m & 1) * 16));
                LDSM_X4(Bf[0][0], Bf[0][1], Bf[1][0], Bf[1][1], tbb + off);
            }
            {
                int m = lane >> 3;
                int n = wn + 16 + (m >> 1) * 8 + (lane & 7);
                uint32_t off = SWZ((uint32_t)(n * 128 + ks * 32 + (m & 1) * 16));
                LDSM_X4(Bf[2][0], Bf[2][1], Bf[3][0], Bf[3][1], tbb + off);
            }
            {
                int n = wn + 32 + (lane & 7);
                uint32_t off = SWZ((uint32_t)(n * 128 + ks * 32 + ((lane >> 3) & 1) * 16));
                LDSM_X2(Bf[4][0], Bf[4][1], tbb + off);
            }
#pragma unroll
            for (int mt = 0; mt < 2; mt++) {
                int r = wm + mt * 16 + (lane & 15);
                uint32_t aoff = SWZ((uint32_t)(r * 128 + ks * 32 + (lane >> 4) * 16));
                uint32_t A0, A1, A2, A3;
                LDSM_X4(A0, A1, A2, A3, ta + aoff);
#pragma unroll
                for (int nt = 0; nt < 5; nt++)
                    MMAF16(acc[mt][nt], A0, A1, A2, A3, Bf[nt][0], Bf[nt][1]);
            }
        }
    }

    // ---- epilogue: s = relu(h2 + pb2) . w3, reduce, clip, write --------
    float part[2][2] = {{0.f, 0.f}, {0.f, 0.f}};
#pragma unroll
    for (int nt = 0; nt < 5; nt++) {
        int c = wn + nt * 8 + (lane & 3) * 2;
        float b0 = 0.f, w0 = 0.f, b1 = 0.f, w1 = 0.f;
        if (c < 150)     { b0 = pb2[c];     w0 = w3[c]; }
        if (c + 1 < 150) { b1 = pb2[c + 1]; w1 = w3[c + 1]; }
#pragma unroll
        for (int mt = 0; mt < 2; mt++)
#pragma unroll
            for (int h = 0; h < 2; h++) {
                part[mt][h] += fmaxf(acc[mt][nt][h * 2] + b0, 0.f) * w0
                             + fmaxf(acc[mt][nt][h * 2 + 1] + b1, 0.f) * w1;
            }
    }
#pragma unroll
    for (int mt = 0; mt < 2; mt++)
#pragma unroll
        for (int h = 0; h < 2; h++) {
            part[mt][h] += __shfl_xor_sync(0xffffffff, part[mt][h], 1);
            part[mt][h] += __shfl_xor_sync(0xffffffff, part[mt][h], 2);
        }
    if ((lane & 3) == 0) {
#pragma unroll
        for (int mt = 0; mt < 2; mt++)
#pragma unroll
            for (int h = 0; h < 2; h++) {
                int row = wm + mt * 16 + (lane >> 2) + h * 8;
                sRed[row * 4 + (wid & 3)] = part[mt][h];
            }
    }
    __syncthreads();
    if (tid < 64) {
        float s = pb3[0] + sRed[tid * 4] + sRed[tid * 4 + 1]
                + sRed[tid * 4 + 2] + sRed[tid * 4 + 3];
        long pr = p0 + tid;
        int jj = (int)(pr & 255);
        float v = (mm[i_fix] + mm[jj] + s) * (1.f / 3.f);
        v = fminf(fmaxf(v, 0.f), 1.f);
        out[pr] = v;
    }
}

// ---------------- launch ------------------------------------------------
extern "C" void kernel_launch(void* const* d_in, const int* in_sizes, int n_in,
                              void* d_out, int out_size)
{
    const float* e   = (const float*)d_in[0];
    const int*   sp  = (const int*)d_in[1];
    const int*   wd  = (const int*)d_in[2];
    const float* aW1 = (const float*)d_in[3];
    const float* ab1 = (const float*)d_in[4];
    const float* aW2 = (const float*)d_in[5];
    const float* ab2 = (const float*)d_in[6];
    const float* aW3 = (const float*)d_in[7];
    const float* ab3 = (const float*)d_in[8];
    const float* mW1 = (const float*)d_in[9];
    const float* mb1 = (const float*)d_in[10];
    const float* mW2 = (const float*)d_in[11];
    const float* mb2 = (const float*)d_in[12];
    const float* mW3 = (const float*)d_in[13];
    const float* mb3 = (const float*)d_in[14];
    const float* pW1 = (const float*)d_in[15];
    const float* pb1 = (const float*)d_in[16];
    const float* pW2 = (const float*)d_in[17];
    const float* pb2 = (const float*)d_in[18];
    const float* pW3 = (const float*)d_in[19];
    const float* pb3 = (const float*)d_in[20];
    float* out = (float*)d_out;

    cudaFuncSetAttribute(pair_h1_mma, cudaFuncAttributeMaxDynamicSharedMemorySize,
                         PH1_SMEM);
    cudaFuncSetAttribute(pair_out_mma, cudaFuncAttributeMaxDynamicSharedMemorySize,
                         PO_SMEM);
    cudaFuncSetAttribute(tok2_attn_we_kernel,
                         cudaFuncAttributeMaxDynamicSharedMemorySize, TOK2_SMEM);

    // weight preps (independent)
    prep_weights<<<1440, 256>>>(pW1 + 4608L * 150, pW2);

    // token MLP layer 1: split-K (6 x 128) -> partials
    gemm_split<<<dim3(32, 6, 1), 256>>>(e, 0, 768, aW1, nullptr, nullptr,
                                        OFF_PART, 2048, 128);
    // fused reduce + layer2 + attn + we (single-shot smem)
    tok2_attn_we_kernel<<<128, 256, TOK2_SMEM>>>(ab1, aW2, ab2, aW3, ab3, e);

    // span features
    gather_g_kernel<<<256, 768>>>(e, sp, wd);

    // fused mh1 / hi / hjb: split-K (12 x 192) x 3 weights -> reduce
    gemm_split<<<dim3(4, 12, 3), 256>>>(nullptr, OFF_G, 2304,
                                        mW1, pW1, pW1 + 2304L * 150,
                                        OFF_PART, 256, 192);
    reduce_3<<<dim3(256, 3), 160>>>(mb1, pb1);

    // lower-triangle hij on tensor cores (f32-acc, 4 j's per CTA)
    pair_h1_mma<<<dim3(64, 4), 512, PH1_SMEM>>>();

    // m tail (fused layer2 + dot)
    mtail_kernel<<<16, 256>>>(mW2, mb2, mW3, mb3);

    // pairwise output on tensor cores
    pair_out_mma<<<1024, 256, PO_SMEM>>>(pb2, pW3, pb3, out);
}

// round 16
// speedup vs baseline: 1.0778x; 1.0778x over previous
#include <cuda_runtime.h>
#include <cuda_fp16.h>
#include <cstdint>

// Problem constants
#define TT 2048
#define EE 768

// ---------------- scratch (device global, zero-init .bss) ----------------
static constexpr long OFF_WE    = 0;
static constexpr long OFF_G     = OFF_WE    + 2048L * 768;
static constexpr long OFF_MH1   = OFF_G     + 256L * 2304;
static constexpr long OFF_M     = OFF_MH1   + 256L * 160;
static constexpr long OFF_HI    = OFF_M     + 256L;
static constexpr long OFF_HJB   = OFF_HI    + 256L * 160;
static constexpr long OFF_H1P   = OFF_HJB   + 256L * 160;
static constexpr long SCRATCH_TOTAL = OFF_H1P + 65536L * 160;
// split-K partial buffers alias the h1p region (consumed before pair_h1)
static constexpr long OFF_PART  = OFF_H1P;

__device__ __align__(16) float g_scratch[SCRATCH_TOTAL];

// Wc transposed, f16: [160 n][2304 k]
__device__ __align__(16) unsigned short g_wct[160L * 2304];
// W2 transposed, f16: [160 n][160 k]
__device__ __align__(16) unsigned short g_w2t[160L * 160];
// mW1 / Wa / Wb transposed, f16: [3 w][160 n][2304 k]
__device__ __align__(16) unsigned short g_w3t[3L * 160 * 2304];

// ======================= helpers ==========================
__device__ __forceinline__ uint32_t smem_u32(const void* p) {
    uint32_t a;
    asm("{ .reg .u64 t; cvta.to.shared.u64 t, %1; cvt.u32.u64 %0, t; }"
        : "=r"(a) : "l"(p));
    return a;
}
#define SWZ(x) ((x) ^ (((x) >> 3) & 0x70))
#define STS128(a0, a1, a2, a3, addr) \
    asm volatile("st.shared.v4.b32 [%0], {%1,%2,%3,%4};" \
                 :: "r"(addr), "r"(a0), "r"(a1), "r"(a2), "r"(a3) : "memory")

__device__ __forceinline__ uint32_t pack_h2(float lo, float hi) {
    uint32_t d;
    asm("cvt.rn.f16x2.f32 %0, %1, %2;" : "=r"(d) : "f"(hi), "f"(lo));
    return d;
}

#define LDSM_X4(r0, r1, r2, r3, a) \
    asm volatile("ldmatrix.sync.aligned.m8n8.x4.shared.b16 {%0,%1,%2,%3}, [%4];" \
                 : "=r"(r0), "=r"(r1), "=r"(r2), "=r"(r3) : "r"(a))
#define LDSM_X2(r0, r1, a) \
    asm volatile("ldmatrix.sync.aligned.m8n8.x2.shared.b16 {%0,%1}, [%2];" \
                 : "=r"(r0), "=r"(r1) : "r"(a))
#define MMAF16(c, A0, A1, A2, A3, B0, B1) \
    asm volatile("mma.sync.aligned.m16n8k16.row.col.f32.f16.f16.f32 " \
                 "{%0,%1,%2,%3}, {%4,%5,%6,%7}, {%8,%9}, {%0,%1,%2,%3};" \
                 : "+f"((c)[0]), "+f"((c)[1]), "+f"((c)[2]), "+f"((c)[3]) \
                 : "r"(A0), "r"(A1), "r"(A2), "r"(A3), "r"(B0), "r"(B1))

// ---------------- weight prep: Wc^T f16 + W2^T f16 ----------------------
__global__ __launch_bounds__(256) void prep_weights(
    const float* __restrict__ Wc, const float* __restrict__ W2)
{
    long idx = (long)blockIdx.x * 256 + threadIdx.x;
    int n = (int)(idx / 2304);
    int k = (int)(idx - (long)n * 2304);
    float w = (n < 150) ? Wc[(long)k * 150 + n] : 0.f;
    g_wct[idx] = __half_as_ushort(__float2half_rn(w));
    if (idx < 160 * 160) {
        int n2 = (int)(idx / 160), k2 = (int)(idx - (long)n2 * 160);
        float w2 = (n2 < 150 && k2 < 150) ? W2[(long)k2 * 150 + n2] : 0.f;
        g_w2t[idx] = __half_as_ushort(__float2half_rn(w2));
    }
}

// ---------------- prep: mW1 / Wa / Wb -> transposed f16 -----------------
__global__ __launch_bounds__(256) void prep_w3(
    const float* __restrict__ mW1, const float* __restrict__ Wa,
    const float* __restrict__ Wb)
{
    long idx = (long)blockIdx.x * 256 + threadIdx.x;   // 0 .. 3*160*2304-1
    if (idx >= 3L * 160 * 2304) return;
    int w = (int)(idx / (160L * 2304));
    long rem = idx - (long)w * 160 * 2304;
    int n = (int)(rem / 2304);
    int k = (int)(rem - (long)n * 2304);
    const float* W = (w == 0) ? mW1 : ((w == 1) ? Wa : Wb);
    float v = (n < 150) ? W[(long)k * 150 + n] : 0.f;
    g_w3t[idx] = __half_as_ushort(__float2half_rn(v));
}

// ---------------- split-K GEMM: partials, no bias/act (token L1) -------
__global__ __launch_bounds__(256) void gemm_split(
    const float* __restrict__ Aext, long aOff, int lda,
    const float* __restrict__ W0,
    long partOff, int Mtot, int kPerSplit)
{
    const float* A = Aext ? Aext : (g_scratch + aOff);
    const float* W = W0;
    float* P = g_scratch + partOff + ((long)blockIdx.y * Mtot) * 160;

    __shared__ float sA[16][68];
    __shared__ float sW[16][160];

    int tid = threadIdx.x;
    int rg = tid >> 4;
    int cg = tid & 15;
    int row0 = blockIdx.x * 64;
    int kbase = blockIdx.y * kPerSplit;

    float acc[4][10];
#pragma unroll
    for (int a = 0; a < 4; a++)
#pragma unroll
        for (int b = 0; b < 10; b++) acc[a][b] = 0.f;

    int nCh = kPerSplit >> 4;
    for (int ch = 0; ch < nCh; ch++) {
        int k0 = kbase + ch * 16;
        {
            int c = tid & 15, r = tid >> 4;
#pragma unroll
            for (int pass = 0; pass < 4; pass++) {
                int rl = pass * 16 + r;
                sA[c][rl] = A[(long)(row0 + rl) * lda + k0 + c];
            }
        }
#pragma unroll
        for (int i = 0; i < 10; i++) {
            int idx = tid + i * 256;
            int k = idx / 160, h = idx - k * 160;
            sW[k][h] = (h < 150) ? W[(long)(k0 + k) * 150 + h] : 0.f;
        }
        __syncthreads();
#pragma unroll
        for (int k = 0; k < 16; k++) {
            float4 a4 = *(const float4*)&sA[k][rg * 4];
            float av0 = a4.x, av1 = a4.y, av2 = a4.z, av3 = a4.w;
#pragma unroll
            for (int hh = 0; hh < 10; hh += 2) {
                float2 w = *(const float2*)&sW[k][cg * 10 + hh];
                acc[0][hh]     += av0 * w.x;  acc[0][hh + 1] += av0 * w.y;
                acc[1][hh]     += av1 * w.x;  acc[1][hh + 1] += av1 * w.y;
                acc[2][hh]     += av2 * w.x;  acc[2][hh + 1] += av2 * w.y;
                acc[3][hh]     += av3 * w.x;  acc[3][hh + 1] += av3 * w.y;
            }
        }
        __syncthreads();
    }

#pragma unroll
    for (int rr = 0; rr < 4; rr++) {
        int row = row0 + rg * 4 + rr;
#pragma unroll
        for (int hh = 0; hh < 10; hh++) {
            int h = cg * 10 + hh;
            if (h < 150) P[(long)row * 160 + h] = acc[rr][hh];
        }
    }
}

// ======== gemm3_tc: mh1/hi/hjb raw partials on tensor cores ============
// Grid (4 mb, 6 ksplit, 3 w). CTA: M=64, N=160, K=384 (6 chunks of 64).
// A = g rows -> f16; B = g_w3t. Partials f32 -> OFF_PART[w][ks][256][160].
#define G3_A 0
#define G3_B 8192
#define G3_BUF 28672
#define G3_SMEM (2 * G3_BUF)

__global__ void __launch_bounds__(256, 2) gemm3_tc()
{
    extern __shared__ __align__(1024) char smem[];
    uint32_t sb = smem_u32(smem);

    const float* g = g_scratch + OFF_G;
    int tid  = threadIdx.x;
    int lane = tid & 31;
    int wid  = tid >> 5;
    int row0 = blockIdx.x * 64;
    int kbase = blockIdx.y * 384;
    int w = blockIdx.z;

    const unsigned short* WT = g_w3t + (long)w * 160 * 2304;
    float* P = g_scratch + OFF_PART + ((long)(w * 6 + blockIdx.y) * 256) * 160;

    int wm = (wid >> 2) * 32;
    int wn = (wid & 3) * 40;

    float acc[2][5][4];
#pragma unroll
    for (int a = 0; a < 2; a++)
#pragma unroll
        for (int b = 0; b < 5; b++)
#pragma unroll
            for (int c = 0; c < 4; c++) acc[a][b][c] = 0.f;

    int arow = tid >> 2;             // 0..63
    int seg  = tid & 3;              // 16 floats each
    const float* gA = g + (long)(row0 + arow) * 2304 + kbase + seg * 16;

    auto stage = [&](int ch) {
        uint32_t tb = sb + (uint32_t)(ch & 1) * G3_BUF;
        int k0 = ch * 64;
        {
            const float4* s4 = (const float4*)(gA + k0);
            float4 a0 = s4[0], a1 = s4[1], a2 = s4[2], a3 = s4[3];
            uint32_t h0 = pack_h2(a0.x, a0.y), h1 = pack_h2(a0.z, a0.w);
            uint32_t h2 = pack_h2(a1.x, a1.y), h3 = pack_h2(a1.z, a1.w);
            uint32_t h4 = pack_h2(a2.x, a2.y), h5 = pack_h2(a2.z, a2.w);
            uint32_t h6 = pack_h2(a3.x, a3.y), h7 = pack_h2(a3.z, a3.w);
            uint32_t off = (uint32_t)(arow * 128 + seg * 32);
            STS128(h0, h1, h2, h3, tb + G3_A + SWZ(off));
            STS128(h4, h5, h6, h7, tb + G3_A + SWZ(off + 16));
        }
#pragma unroll
        for (int t = 0; t < 5; t++) {
            int idx = tid + t * 256;   // 0..1279
            int n = idx >> 3, u = idx & 7;
            uint4 v = *(const uint4*)(WT + (long)n * 2304 + kbase + k0 + u * 8);
            STS128(v.x, v.y, v.z, v.w, tb + G3_B + SWZ((uint32_t)(n * 128 + u * 16)));
        }
    };

    stage(0);
    __syncthreads();

    for (int ch = 0; ch < 6; ch++) {
        if (ch < 5) stage(ch + 1);
        uint32_t tb = sb + (uint32_t)(ch & 1) * G3_BUF;
#pragma unroll
        for (int ks = 0; ks < 4; ks++) {
            uint32_t Bf[5][2];
            {
                int m = lane >> 3;
                int n = wn + (m >> 1) * 8 + (lane & 7);
                uint32_t off = SWZ((uint32_t)(n * 128 + ks * 32 + (m & 1) * 16));
                LDSM_X4(Bf[0][0], Bf[0][1], Bf[1][0], Bf[1][1], tb + G3_B + off);
            }
            {
                int m = lane >> 3;
                int n = wn + 16 + (m >> 1) * 8 + (lane & 7);
                uint32_t off = SWZ((uint32_t)(n * 128 + ks * 32 + (m & 1) * 16));
                LDSM_X4(Bf[2][0], Bf[2][1], Bf[3][0], Bf[3][1], tb + G3_B + off);
            }
            {
                int n = wn + 32 + (lane & 7);
                uint32_t off = SWZ((uint32_t)(n * 128 + ks * 32 + ((lane >> 3) & 1) * 16));
                LDSM_X2(Bf[4][0], Bf[4][1], tb + G3_B + off);
            }
#pragma unroll
            for (int mt = 0; mt < 2; mt++) {
                int r = wm + mt * 16 + (lane & 15);
                uint32_t aoff = SWZ((uint32_t)(r * 128 + ks * 32 + (lane >> 4) * 16));
                uint32_t A0, A1, A2, A3;
                LDSM_X4(A0, A1, A2, A3, tb + G3_A + aoff);
#pragma unroll
                for (int nt = 0; nt < 5; nt++)
                    MMAF16(acc[mt][nt], A0, A1, A2, A3, Bf[nt][0], Bf[nt][1]);
            }
        }
        __syncthreads();
    }

#pragma unroll
    for (int mt = 0; mt < 2; mt++)
#pragma unroll
        for (int nt = 0; nt < 5; nt++) {
            int c = wn + nt * 8 + (lane & 3) * 2;
#pragma unroll
            for (int h = 0; h < 2; h++) {
                int row = row0 + wm + mt * 16 + (lane >> 2) + h * 8;
                *(float2*)(P + (long)row * 160 + c) =
                    make_float2(acc[mt][nt][h * 2], acc[mt][nt][h * 2 + 1]);
            }
        }
}

// ------- fused: token L1-reduce + L2 + attn dot + we (chunked) ----------
__global__ __launch_bounds__(256) void tok2_attn_we_kernel(
    const float* __restrict__ ab1,
    const float* __restrict__ W,  const float* __restrict__ b2,
    const float* __restrict__ w3, const float* __restrict__ b3,
    const float* __restrict__ e)
{
    const float* part = g_scratch + OFF_PART;
    float* we = g_scratch + OFF_WE;

    __shared__ float sA[16][20];
    __shared__ float sW[16][160];
    __shared__ float sRed[16][16];
    __shared__ float sAttn[16];

    int tid = threadIdx.x;
    int rg = tid >> 4;
    int cg = tid & 15;
    int row0 = blockIdx.x * 16;

    float acc[10];
#pragma unroll
    for (int b = 0; b < 10; b++) acc[b] = 0.f;

    for (int ch = 0; ch < 10; ch++) {
        int k0 = ch * 16;
        {
            int c = tid & 15, r = tid >> 4;
            float v = 0.f;
            if (k0 + c < 150) {
                long off = ((long)(row0 + r)) * 160 + k0 + c;
                float s = 0.f;
#pragma unroll
                for (int p = 0; p < 6; p++)
                    s += part[(long)p * 2048 * 160 + off];
                v = fmaxf(s + ab1[k0 + c], 0.f);
            }
            sA[c][r] = v;
        }
#pragma unroll
        for (int i = 0; i < 10; i++) {
            int idx = tid + i * 256;
            int k = idx / 160, h = idx - k * 160;
            float v = 0.f;
            if (k0 + k < 150 && h < 150) v = W[(long)(k0 + k) * 150 + h];
            sW[k][h] = v;
        }
        __syncthreads();
#pragma unroll
        for (int k = 0; k < 16; k++) {
            float av = sA[k][rg];
#pragma unroll
            for (int hh = 0; hh < 10; hh += 2) {
                float2 w = *(const float2*)&sW[k][cg * 10 + hh];
                acc[hh]     += av * w.x;
                acc[hh + 1] += av * w.y;
            }
        }
        __syncthreads();
    }

    float partd = 0.f;
#pragma unroll
    for (int hh = 0; hh < 10; hh++) {
        int h = cg * 10 + hh;
        if (h < 150) partd += fmaxf(acc[hh] + b2[h], 0.f) * w3[h];
    }
    sRed[rg][cg] = partd;
    __syncthreads();
    if (tid < 16) {
        float s = b3[0];
#pragma unroll
        for (int c = 0; c < 16; c++) s += sRed[tid][c];
        sAttn[tid] = s;
    }
    __syncthreads();
#pragma unroll
    for (int it = 0; it < 48; it++) {
        int lin = it * 256 + tid;
        int r = lin / 768, c = lin - r * 768;
        long t = row0 + r;
        we[t * 768 + c] = e[t * 768 + c] * sAttn[r];
    }
}

// ---------------- m tail: m = relu(mh1@mW2+mb2).mW3 + mb3 ---------------
__global__ __launch_bounds__(256) void mtail_kernel(
    const float* __restrict__ W,  const float* __restrict__ b2,
    const float* __restrict__ w3, const float* __restrict__ b3)
{
    const float* A = g_scratch + OFF_MH1;
    float* mo = g_scratch + OFF_M;

    __shared__ float sA[16][20];
    __shared__ float sW[16][160];
    __shared__ float sRed[16][16];

    int tid = threadIdx.x;
    int rg = tid >> 4;
    int cg = tid & 15;
    int row0 = blockIdx.x * 16;

    float acc[10];
#pragma unroll
    for (int b = 0; b < 10; b++) acc[b] = 0.f;

    for (int ch = 0; ch < 10; ch++) {
        int k0 = ch * 16;
        {
            int c = tid & 15, r = tid >> 4;
            float v = 0.f;
            if (k0 + c < 150) v = A[(long)(row0 + r) * 160 + k0 + c];
            sA[c][r] = v;
        }
#pragma unroll
        for (int i = 0; i < 10; i++) {
            int idx = tid + i * 256;
            int k = idx / 160, h = idx - k * 160;
            float v = 0.f;
            if (k0 + k < 150 && h < 150) v = W[(long)(k0 + k) * 150 + h];
            sW[k][h] = v;
        }
        __syncthreads();
#pragma unroll
        for (int k = 0; k < 16; k++) {
            float av = sA[k][rg];
#pragma unroll
            for (int hh = 0; hh < 10; hh += 2) {
                float2 w = *(const float2*)&sW[k][cg * 10 + hh];
                acc[hh]     += av * w.x;
                acc[hh + 1] += av * w.y;
            }
        }
        __syncthreads();
    }

    float partd = 0.f;
#pragma unroll
    for (int hh = 0; hh < 10; hh++) {
        int h = cg * 10 + hh;
        if (h < 150) partd += fmaxf(acc[hh] + b2[h], 0.f) * w3[h];
    }
    sRed[rg][cg] = partd;
    __syncthreads();
    if (tid < 16) {
        float s = b3[0];
#pragma unroll
        for (int c = 0; c < 16; c++) s += sRed[tid][c];
        mo[row0 + tid] = s;
    }
}

// ---------------- 3-way reduce: mh1 / hi / hjb (6 partials) -------------
__global__ __launch_bounds__(160) void reduce_3(
    const float* __restrict__ mb1, const float* __restrict__ pb1)
{
    int row = blockIdx.x, z = blockIdx.y, c = threadIdx.x;
    float s = 0.f;
    if (c < 150) {
#pragma unroll
        for (int k = 0; k < 6; k++)
            s += g_scratch[OFF_PART + ((long)(z * 6 + k) * 256 + row) * 160 + c];
    }
    if (z == 0) {
        float v = (c < 150) ? fmaxf(s + mb1[c], 0.f) : 0.f;
        g_scratch[OFF_MH1 + (long)row * 160 + c] = v;
    } else if (z == 1) {
        g_scratch[OFF_HI + (long)row * 160 + c] = s;
    } else {
        float v = s + ((c < 150) ? pb1[c] : 0.f);
        g_scratch[OFF_HJB + (long)row * 160 + c] = v;
    }
}

// ---------------- g = [e_start | e_end | span_sum], 768 thr/blk ---------
__global__ __launch_bounds__(768) void gather_g_kernel(
    const float* __restrict__ e,
    const int* __restrict__ sp, const int* __restrict__ wd)
{
    const float* we = g_scratch + OFF_WE;
    float* g = g_scratch + OFF_G;
    int s = blockIdx.x, c = threadIdx.x;
    int st = sp[s];
    int en = st + wd[s];
    if (en > TT - 1) en = TT - 1;
    if (en < 0) en = 0;
    g[(long)s * 2304 + c]        = e[(long)st * 768 + c];
    g[(long)s * 2304 + 768 + c]  = e[(long)en * 768 + c];
    float sum = 0.f;
    for (int t = st; t <= en; t++) sum += we[(long)t * 768 + c];
    g[(long)s * 2304 + 1536 + c] = sum;
}

// ================= pair_h1: lower-triangle hij, f16 f32-acc mma =========
#define PH1_A  0
#define PH1_B  32768
#define PH1_BUF 53248
#define PH1_SMEM (2 * PH1_BUF)

__global__ void __launch_bounds__(512, 1) pair_h1_mma()
{
    extern __shared__ __align__(1024) char smem[];
    uint32_t sb = smem_u32(smem);

    const float* g = g_scratch + OFF_G;
    float* h1p     = g_scratch + OFF_H1P;

    int tid  = threadIdx.x;
    int lane = tid & 31;
    int wid  = tid >> 5;
    int jq   = blockIdx.x;
    int ib   = blockIdx.y;

    int j0 = jq * 4;
    int fj = j0 & ~15;
    int i0 = fj + ib * 64;
    if (i0 >= 256) return;
    int M = 256 - i0;
    if (M > 64) M = 64;

    int jsel = wid >> 2;
    int wn   = (wid & 3) * 40;

    float acc[4][5][4];
#pragma unroll
    for (int a = 0; a < 4; a++)
#pragma unroll
        for (int b = 0; b < 5; b++)
#pragma unroll
            for (int c = 0; c < 4; c++) acc[a][b][c] = 0.f;

    int arow = tid >> 3;
    int seg  = tid & 7;
    int gi_row = i0 + arow; if (gi_row > 255) gi_row = 255;
    const float* gi_base = g + (long)gi_row * 2304 + seg * 8;

    auto stage = [&](int ch) {
        uint32_t tb = sb + (uint32_t)(ch & 1) * PH1_BUF;
        int k0 = ch * 64;
        {
            const float4* gi4 = (const float4*)(gi_base + k0);
            float4 a0 = gi4[0], a1 = gi4[1];
            uint32_t sw = SWZ((uint32_t)(arow * 128 + seg * 16));
#pragma unroll
            for (int jj = 0; jj < 4; jj++) {
                const float4* gj4 =
                    (const float4*)(g + (long)(j0 + jj) * 2304 + seg * 8 + k0);
                float4 w0 = gj4[0], w1 = gj4[1];
                uint32_t h01 = pack_h2(a0.x * w0.x, a0.y * w0.y);
                uint32_t h23 = pack_h2(a0.z * w0.z, a0.w * w0.w);
                uint32_t h45 = pack_h2(a1.x * w1.x, a1.y * w1.y);
                uint32_t h67 = pack_h2(a1.z * w1.z, a1.w * w1.w);
                STS128(h01, h23, h45, h67,
                       tb + PH1_A + (uint32_t)jj * 8192 + sw);
            }
        }
#pragma unroll
        for (int t = 0; t < 3; t++) {
            int idx = tid + t * 512;
            if (idx < 1280) {
                int n = idx >> 3, u = idx & 7;
                uint4 v = *(const uint4*)(g_wct + (long)n * 2304 + k0 + u * 8);
                uint32_t sw = SWZ((uint32_t)(n * 128 + u * 16));
                STS128(v.x, v.y, v.z, v.w, tb + PH1_B + sw);
            }
        }
    };

    stage(0);
    __syncthreads();

    for (int ch = 0; ch < 36; ch++) {
        if (ch < 35) stage(ch + 1);
        uint32_t tb = sb + (uint32_t)(ch & 1) * PH1_BUF;
        uint32_t ta = tb + PH1_A + (uint32_t)jsel * 8192;
#pragma unroll
        for (int ks = 0; ks < 4; ks++) {
            uint32_t Bf[5][2];
            {
                int m = lane >> 3;
                int n = wn + (m >> 1) * 8 + (lane & 7);
                uint32_t off = SWZ((uint32_t)(n * 128 + ks * 32 + (m & 1) * 16));
                LDSM_X4(Bf[0][0], Bf[0][1], Bf[1][0], Bf[1][1], tb + PH1_B + off);
            }
            {
                int m = lane >> 3;
                int n = wn + 16 + (m >> 1) * 8 + (lane & 7);
                uint32_t off = SWZ((uint32_t)(n * 128 + ks * 32 + (m & 1) * 16));
                LDSM_X4(Bf[2][0], Bf[2][1], Bf[3][0], Bf[3][1], tb + PH1_B + off);
            }
            {
                int n = wn + 32 + (lane & 7);
                uint32_t off = SWZ((uint32_t)(n * 128 + ks * 32 + ((lane >> 3) & 1) * 16));
                LDSM_X2(Bf[4][0], Bf[4][1], tb + PH1_B + off);
            }
#pragma unroll
            for (int mt = 0; mt < 4; mt++) {
                if (mt * 16 >= M) continue;
                int r = mt * 16 + (lane & 15);
                uint32_t aoff = SWZ((uint32_t)(r * 128 + ks * 32 + (lane >> 4) * 16));
                uint32_t A0, A1, A2, A3;
                LDSM_X4(A0, A1, A2, A3, ta + aoff);
#pragma unroll
                for (int nt = 0; nt < 5; nt++)
                    MMAF16(acc[mt][nt], A0, A1, A2, A3, Bf[nt][0], Bf[nt][1]);
            }
        }
        __syncthreads();
    }

    {
        int j = j0 + jsel;
#pragma unroll
        for (int mt = 0; mt < 4; mt++) {
            if (mt * 16 >= M) continue;
#pragma unroll
            for (int nt = 0; nt < 5; nt++) {
                int c = wn + nt * 8 + (lane & 3) * 2;
#pragma unroll
                for (int h = 0; h < 2; h++) {
                    int i = i0 + mt * 16 + (lane >> 2) + h * 8;
                    *(float2*)(h1p + ((long)i * 256 + j) * 160 + c) =
                        make_float2(acc[mt][nt][h * 2], acc[mt][nt][h * 2 + 1]);
                }
            }
        }
    }
}

// ============ pair_out on tensor cores (64 pairs/CTA, f16) ==============
#define PO_A 0
#define PO_B 24576
#define PO_RED 86016
#define PO_SMEM (86016 + 64 * 4 * 4)

__global__ void __launch_bounds__(256, 2) pair_out_mma(
    const float* __restrict__ pb2, const float* __restrict__ w3,
    const float* __restrict__ pb3, float* __restrict__ out)
{
    extern __shared__ __align__(1024) char smem[];
    uint32_t sb = smem_u32(smem);
    float* sRed = (float*)(smem + PO_RED);     // [64][4]

    const float* h1p = g_scratch + OFF_H1P;
    const float* mm  = g_scratch + OFF_M;
    const float* hi  = g_scratch + OFF_HI;
    const float* hjb = g_scratch + OFF_HJB;

    int tid  = threadIdx.x;
    int lane = tid & 31;
    int wid  = tid >> 5;
    long p0 = (long)blockIdx.x * 64;
    int i_fix = (int)(p0 >> 8);
    int j0 = (int)(p0 & 255);

    int wm = (wid >> 2) * 32;
    int wn = (wid & 3) * 40;

    // ---- stage A: assemble h1 = relu(hij + hi + hjb), f16, swizzled ----
    {
        const float* hirow = hi + (long)i_fix * 160;
#pragma unroll
        for (int t = 0; t < 8; t++) {
            int idx = tid + t * 256;
            int p = idx >> 5, seg = idx & 31;
            if (seg < 20) {
                int j = j0 + p;
                long src = (j <= i_fix) ? ((long)i_fix * 256 + j)
                                        : ((long)j * 256 + i_fix);
                int kc = seg * 8;
                const float4* s4 = (const float4*)(h1p + src * 160 + kc);
                const float4* h4 = (const float4*)(hirow + kc);
                const float4* b4 = (const float4*)(hjb + (long)j * 160 + kc);
                float4 x0 = s4[0], x1 = s4[1];
                float4 y0 = h4[0], y1 = h4[1];
                float4 z0 = b4[0], z1 = b4[1];
                float f0 = fmaxf(x0.x + y0.x + z0.x, 0.f);
                float f1 = fmaxf(x0.y + y0.y + z0.y, 0.f);
                float f2 = fmaxf(x0.z + y0.z + z0.z, 0.f);
                float f3 = fmaxf(x0.w + y0.w + z0.w, 0.f);
                float f4 = fmaxf(x1.x + y1.x + z1.x, 0.f);
                float f5 = fmaxf(x1.y + y1.y + z1.y, 0.f);
                float f6 = fmaxf(x1.z + y1.z + z1.z, 0.f);
                float f7 = fmaxf(x1.w + y1.w + z1.w, 0.f);
                uint32_t h01 = pack_h2(f0, f1), h23 = pack_h2(f2, f3);
                uint32_t h45 = pack_h2(f4, f5), h67 = pack_h2(f6, f7);
                int kblk = seg >> 3, uu = seg & 7;
                uint32_t addr = sb + PO_A + (uint32_t)kblk * 8192
                              + SWZ((uint32_t)(p * 128 + uu * 16));
                STS128(h01, h23, h45, h67, addr);
            }
        }
    }
    // ---- stage B: W2^T f16 ----
    {
#pragma unroll
        for (int t = 0; t < 15; t++) {
            int idx = tid + t * 256;
            if (idx < 3840) {
                int n = idx / 24, u = idx - n * 24;
                int kblk = u >> 3, uu = u & 7;
                int k0 = kblk * 64 + uu * 8;
                uint4 v = make_uint4(0, 0, 0, 0);
                if (k0 < 160) v = *(const uint4*)(g_w2t + (long)n * 160 + k0);
                uint32_t addr = sb + PO_B + (uint32_t)kblk * 20480
                              + SWZ((uint32_t)(n * 128 + uu * 16));
                STS128(v.x, v.y, v.z, v.w, addr);
            }
        }
    }
    __syncthreads();

    float acc[2][5][4];
#pragma unroll
    for (int a = 0; a < 2; a++)
#pragma unroll
        for (int b = 0; b < 5; b++)
#pragma unroll
            for (int c = 0; c < 4; c++) acc[a][b][c] = 0.f;

#pragma unroll
    for (int kblk = 0; kblk < 3; kblk++) {
        uint32_t ta = sb + PO_A + (uint32_t)kblk * 8192;
        uint32_t tbb = sb + PO_B + (uint32_t)kblk * 20480;
        int kmax = (kblk == 2) ? 2 : 4;
#pragma unroll
        for (int ks = 0; ks < 4; ks++) {
            if (ks >= kmax) break;
            uint32_t Bf[5][2];
            {
                int m = lane >> 3;
                int n = wn + (m >> 1) * 8 + (lane & 7);
                uint32_t off = SWZ((uint32_t)(n * 128 + ks * 32 + (m & 1) * 16));
                LDSM_X4(Bf[0][0], Bf[0][1], Bf[1][0], Bf[1][1], tbb + off);
            }
            {
                int m = lane >> 3;
                int n = wn + 16 + (m >> 1) * 8 + (lane & 7);
                uint32_t off = SWZ((uint32_t)(n * 128 + ks * 32 + (m & 1) * 16));
                LDSM_X4(Bf[2][0], Bf[2][1], Bf[3][0], Bf[3][1], tbb + off);
            }
            {
                int n = wn + 32 + (lane & 7);
                uint32_t off = SWZ((uint32_t)(n * 128 + ks * 32 + ((lane >> 3) & 1) * 16));
                LDSM_X2(Bf[4][0], Bf[4][1], tbb + off);
            }
#pragma unroll
            for (int mt = 0; mt < 2; mt++) {
                int r = wm + mt * 16 + (lane & 15);
                uint32_t aoff = SWZ((uint32_t)(r * 128 + ks * 32 + (lane >> 4) * 16));
                uint32_t A0, A1, A2, A3;
                LDSM_X4(A0, A1, A2, A3, ta + aoff);
#pragma unroll
                for (int nt = 0; nt < 5; nt++)
                    MMAF16(acc[mt][nt], A0, A1, A2, A3, Bf[nt][0], Bf[nt][1]);
            }
        }
    }

    // ---- epilogue: s = relu(h2 + pb2) . w3, reduce, clip, write --------
    float part[2][2] = {{0.f, 0.f}, {0.f, 0.f}};
#pragma unroll
    for (int nt = 0; nt < 5; nt++) {
        int c = wn + nt * 8 + (lane & 3) * 2;
        float b0 = 0.f, w0 = 0.f, b1 = 0.f, w1 = 0.f;
        if (c < 150)     { b0 = pb2[c];     w0 = w3[c]; }
        if (c + 1 < 150) { b1 = pb2[c + 1]; w1 = w3[c + 1]; }
#pragma unroll
        for (int mt = 0; mt < 2; mt++)
#pragma unroll
            for (int h = 0; h < 2; h++) {
                part[mt][h] += fmaxf(acc[mt][nt][h * 2] + b0, 0.f) * w0
                             + fmaxf(acc[mt][nt][h * 2 + 1] + b1, 0.f) * w1;
            }
    }
#pragma unroll
    for (int mt = 0; mt < 2; mt++)
#pragma unroll
        for (int h = 0; h < 2; h++) {
            part[mt][h] += __shfl_xor_sync(0xffffffff, part[mt][h], 1);
            part[mt][h] += __shfl_xor_sync(0xffffffff, part[mt][h], 2);
        }
    if ((lane & 3) == 0) {
#pragma unroll
        for (int mt = 0; mt < 2; mt++)
#pragma unroll
            for (int h = 0; h < 2; h++) {
                int row = wm + mt * 16 + (lane >> 2) + h * 8;
                sRed[row * 4 + (wid & 3)] = part[mt][h];
            }
    }
    __syncthreads();
    if (tid < 64) {
        float s = pb3[0] + sRed[tid * 4] + sRed[tid * 4 + 1]
                + sRed[tid * 4 + 2] + sRed[tid * 4 + 3];
        long pr = p0 + tid;
        int jj = (int)(pr & 255);
        float v = (mm[i_fix] + mm[jj] + s) * (1.f / 3.f);
        v = fminf(fmaxf(v, 0.f), 1.f);
        out[pr] = v;
    }
}

// ---------------- launch ------------------------------------------------
extern "C" void kernel_launch(void* const* d_in, const int* in_sizes, int n_in,
                              void* d_out, int out_size)
{
    const float* e   = (const float*)d_in[0];
    const int*   sp  = (const int*)d_in[1];
    const int*   wd  = (const int*)d_in[2];
    const float* aW1 = (const float*)d_in[3];
    const float* ab1 = (const float*)d_in[4];
    const float* aW2 = (const float*)d_in[5];
    const float* ab2 = (const float*)d_in[6];
    const float* aW3 = (const float*)d_in[7];
    const float* ab3 = (const float*)d_in[8];
    const float* mW1 = (const float*)d_in[9];
    const float* mb1 = (const float*)d_in[10];
    const float* mW2 = (const float*)d_in[11];
    const float* mb2 = (const float*)d_in[12];
    const float* mW3 = (const float*)d_in[13];
    const float* mb3 = (const float*)d_in[14];
    const float* pW1 = (const float*)d_in[15];
    const float* pb1 = (const float*)d_in[16];
    const float* pW2 = (const float*)d_in[17];
    const float* pb2 = (const float*)d_in[18];
    const float* pW3 = (const float*)d_in[19];
    const float* pb3 = (const float*)d_in[20];
    float* out = (float*)d_out;

    cudaFuncSetAttribute(pair_h1_mma, cudaFuncAttributeMaxDynamicSharedMemorySize,
                         PH1_SMEM);
    cudaFuncSetAttribute(pair_out_mma, cudaFuncAttributeMaxDynamicSharedMemorySize,
                         PO_SMEM);
    cudaFuncSetAttribute(gemm3_tc, cudaFuncAttributeMaxDynamicSharedMemorySize,
                         G3_SMEM);

    // weight preps (independent)
    prep_weights<<<1440, 256>>>(pW1 + 4608L * 150, pW2);
    prep_w3<<<4320, 256>>>(mW1, pW1, pW1 + 2304L * 150);

    // token MLP layer 1: split-K (6 x 128) -> partials
    gemm_split<<<dim3(32, 6, 1), 256>>>(e, 0, 768, aW1, OFF_PART, 2048, 128);
    // fused reduce + layer2 + attn + we
    tok2_attn_we_kernel<<<128, 256>>>(ab1, aW2, ab2, aW3, ab3, e);

    // span features
    gather_g_kernel<<<256, 768>>>(e, sp, wd);

    // mh1 / hi / hjb on tensor cores: split-K (6 x 384) x 3 weights
    gemm3_tc<<<dim3(4, 6, 3), 256, G3_SMEM>>>();
    reduce_3<<<dim3(256, 3), 160>>>(mb1, pb1);

    // lower-triangle hij on tensor cores (f32-acc, 4 j's per CTA)
    pair_h1_mma<<<dim3(64, 4), 512, PH1_SMEM>>>();

    // m tail (fused layer2 + dot)
    mtail_kernel<<<16, 256>>>(mW2, mb2, mW3, mb3);

    // pairwise output on tensor cores
    pair_out_mma<<<1024, 256, PO_SMEM>>>(pb2, pW3, pb3, out);
}

// round 17
// speedup vs baseline: 1.1355x; 1.0535x over previous
#include <cuda_runtime.h>
#include <cuda_fp16.h>
#include <cstdint>

// Problem constants
#define TT 2048
#define EE 768

// ---------------- scratch (device global, zero-init .bss) ----------------
static constexpr long OFF_WE    = 0;
static constexpr long OFF_G     = OFF_WE    + 2048L * 768;
static constexpr long OFF_MH1   = OFF_G     + 256L * 2304;
static constexpr long OFF_M     = OFF_MH1   + 256L * 160;
static constexpr long OFF_HI    = OFF_M     + 256L;
static constexpr long OFF_HJB   = OFF_HI    + 256L * 160;
static constexpr long OFF_H1P   = OFF_HJB   + 256L * 160;
static constexpr long SCRATCH_TOTAL = OFF_H1P + 65536L * 160;
// regions aliasing h1p (all consumed before pair_h1 writes it)
static constexpr long OFF_PART   = OFF_H1P;                   // gemm3 partials
static constexpr long OFF_H1TOK  = OFF_H1P + 4000000L;        // token L1 out

__device__ __align__(16) float g_scratch[SCRATCH_TOTAL];

// Wc transposed, f16: [160 n][2304 k]
__device__ __align__(16) unsigned short g_wct[160L * 2304];
// W2 transposed, f16: [160 n][160 k]
__device__ __align__(16) unsigned short g_w2t[160L * 160];
// mW1 / Wa / Wb transposed, f16: [3 w][160 n][2304 k]
__device__ __align__(16) unsigned short g_w3t[3L * 160 * 2304];
// aW1 transposed f16: [160 n][768 k]; aW2 transposed f16: [160 n][160 k]
__device__ __align__(16) unsigned short g_aw1t[160L * 768];
__device__ __align__(16) unsigned short g_aw2t[160L * 160];

// ======================= helpers ==========================
__device__ __forceinline__ uint32_t smem_u32(const void* p) {
    uint32_t a;
    asm("{ .reg .u64 t; cvta.to.shared.u64 t, %1; cvt.u32.u64 %0, t; }"
        : "=r"(a) : "l"(p));
    return a;
}
#define SWZ(x) ((x) ^ (((x) >> 3) & 0x70))
#define STS128(a0, a1, a2, a3, addr) \
    asm volatile("st.shared.v4.b32 [%0], {%1,%2,%3,%4};" \
                 :: "r"(addr), "r"(a0), "r"(a1), "r"(a2), "r"(a3) : "memory")

__device__ __forceinline__ uint32_t pack_h2(float lo, float hi) {
    uint32_t d;
    asm("cvt.rn.f16x2.f32 %0, %1, %2;" : "=r"(d) : "f"(hi), "f"(lo));
    return d;
}

#define LDSM_X4(r0, r1, r2, r3, a) \
    asm volatile("ldmatrix.sync.aligned.m8n8.x4.shared.b16 {%0,%1,%2,%3}, [%4];" \
                 : "=r"(r0), "=r"(r1), "=r"(r2), "=r"(r3) : "r"(a))
#define LDSM_X2(r0, r1, a) \
    asm volatile("ldmatrix.sync.aligned.m8n8.x2.shared.b16 {%0,%1}, [%2];" \
                 : "=r"(r0), "=r"(r1) : "r"(a))
#define MMAF16(c, A0, A1, A2, A3, B0, B1) \
    asm volatile("mma.sync.aligned.m16n8k16.row.col.f32.f16.f16.f32 " \
                 "{%0,%1,%2,%3}, {%4,%5,%6,%7}, {%8,%9}, {%0,%1,%2,%3};" \
                 : "+f"((c)[0]), "+f"((c)[1]), "+f"((c)[2]), "+f"((c)[3]) \
                 : "r"(A0), "r"(A1), "r"(A2), "r"(A3), "r"(B0), "r"(B1))

// ---------------- weight prep: Wc^T f16 + W2^T f16 ----------------------
__global__ __launch_bounds__(256) void prep_weights(
    const float* __restrict__ Wc, const float* __restrict__ W2)
{
    long idx = (long)blockIdx.x * 256 + threadIdx.x;
    int n = (int)(idx / 2304);
    int k = (int)(idx - (long)n * 2304);
    float w = (n < 150) ? Wc[(long)k * 150 + n] : 0.f;
    g_wct[idx] = __half_as_ushort(__float2half_rn(w));
    if (idx < 160 * 160) {
        int n2 = (int)(idx / 160), k2 = (int)(idx - (long)n2 * 160);
        float w2 = (n2 < 150 && k2 < 150) ? W2[(long)k2 * 150 + n2] : 0.f;
        g_w2t[idx] = __half_as_ushort(__float2half_rn(w2));
    }
}

// ---------------- prep: mW1 / Wa / Wb -> transposed f16 -----------------
__global__ __launch_bounds__(256) void prep_w3(
    const float* __restrict__ mW1, const float* __restrict__ Wa,
    const float* __restrict__ Wb)
{
    long idx = (long)blockIdx.x * 256 + threadIdx.x;
    if (idx >= 3L * 160 * 2304) return;
    int w = (int)(idx / (160L * 2304));
    long rem = idx - (long)w * 160 * 2304;
    int n = (int)(rem / 2304);
    int k = (int)(rem - (long)n * 2304);
    const float* W = (w == 0) ? mW1 : ((w == 1) ? Wa : Wb);
    float v = (n < 150) ? W[(long)k * 150 + n] : 0.f;
    g_w3t[idx] = __half_as_ushort(__float2half_rn(v));
}

// ---------------- prep: aW1^T, aW2^T f16 --------------------------------
__global__ __launch_bounds__(256) void prep_w12(
    const float* __restrict__ aW1, const float* __restrict__ aW2)
{
    long idx = (long)blockIdx.x * 256 + threadIdx.x;
    if (idx < 160L * 768) {
        int n = (int)(idx / 768), k = (int)(idx - (long)n * 768);
        float v = (n < 150) ? aW1[(long)k * 150 + n] : 0.f;
        g_aw1t[idx] = __half_as_ushort(__float2half_rn(v));
    }
    if (idx < 160 * 160) {
        int n = (int)(idx / 160), k = (int)(idx - (long)n * 160);
        float v = (n < 150 && k < 150) ? aW2[(long)k * 150 + n] : 0.f;
        g_aw2t[idx] = __half_as_ushort(__float2half_rn(v));
    }
}

// ======== tok1_tc: h1tok = relu(e @ aW1 + ab1), tensor cores ============
// Grid 32. CTA: M=64 tokens, N=160, K=768 (12 chunks of 64).
#define G3_A 0
#define G3_B 8192
#define G3_BUF 28672
#define G3_SMEM (2 * G3_BUF)

__global__ void __launch_bounds__(256, 2) tok1_tc(
    const float* __restrict__ e, const float* __restrict__ ab1)
{
    extern __shared__ __align__(1024) char smem[];
    uint32_t sb = smem_u32(smem);

    int tid  = threadIdx.x;
    int lane = tid & 31;
    int wid  = tid >> 5;
    int row0 = blockIdx.x * 64;
    float* H = g_scratch + OFF_H1TOK;

    int wm = (wid >> 2) * 32;
    int wn = (wid & 3) * 40;

    float acc[2][5][4];
#pragma unroll
    for (int a = 0; a < 2; a++)
#pragma unroll
        for (int b = 0; b < 5; b++)
#pragma unroll
            for (int c = 0; c < 4; c++) acc[a][b][c] = 0.f;

    int arow = tid >> 2;
    int seg  = tid & 3;
    const float* gA = e + (long)(row0 + arow) * 768 + seg * 16;

    auto stage = [&](int ch) {
        uint32_t tb = sb + (uint32_t)(ch & 1) * G3_BUF;
        int k0 = ch * 64;
        {
            const float4* s4 = (const float4*)(gA + k0);
            float4 a0 = s4[0], a1 = s4[1], a2 = s4[2], a3 = s4[3];
            uint32_t h0 = pack_h2(a0.x, a0.y), h1 = pack_h2(a0.z, a0.w);
            uint32_t h2 = pack_h2(a1.x, a1.y), h3 = pack_h2(a1.z, a1.w);
            uint32_t h4 = pack_h2(a2.x, a2.y), h5 = pack_h2(a2.z, a2.w);
            uint32_t h6 = pack_h2(a3.x, a3.y), h7 = pack_h2(a3.z, a3.w);
            uint32_t off = (uint32_t)(arow * 128 + seg * 32);
            STS128(h0, h1, h2, h3, tb + G3_A + SWZ(off));
            STS128(h4, h5, h6, h7, tb + G3_A + SWZ(off + 16));
        }
#pragma unroll
        for (int t = 0; t < 5; t++) {
            int idx = tid + t * 256;
            int n = idx >> 3, u = idx & 7;
            uint4 v = *(const uint4*)(g_aw1t + (long)n * 768 + k0 + u * 8);
            STS128(v.x, v.y, v.z, v.w, tb + G3_B + SWZ((uint32_t)(n * 128 + u * 16)));
        }
    };

    stage(0);
    __syncthreads();

    for (int ch = 0; ch < 12; ch++) {
        if (ch < 11) stage(ch + 1);
        uint32_t tb = sb + (uint32_t)(ch & 1) * G3_BUF;
#pragma unroll
        for (int ks = 0; ks < 4; ks++) {
            uint32_t Bf[5][2];
            {
                int m = lane >> 3;
                int n = wn + (m >> 1) * 8 + (lane & 7);
                uint32_t off = SWZ((uint32_t)(n * 128 + ks * 32 + (m & 1) * 16));
                LDSM_X4(Bf[0][0], Bf[0][1], Bf[1][0], Bf[1][1], tb + G3_B + off);
            }
            {
                int m = lane >> 3;
                int n = wn + 16 + (m >> 1) * 8 + (lane & 7);
                uint32_t off = SWZ((uint32_t)(n * 128 + ks * 32 + (m & 1) * 16));
                LDSM_X4(Bf[2][0], Bf[2][1], Bf[3][0], Bf[3][1], tb + G3_B + off);
            }
            {
                int n = wn + 32 + (lane & 7);
                uint32_t off = SWZ((uint32_t)(n * 128 + ks * 32 + ((lane >> 3) & 1) * 16));
                LDSM_X2(Bf[4][0], Bf[4][1], tb + G3_B + off);
            }
#pragma unroll
            for (int mt = 0; mt < 2; mt++) {
                int r = wm + mt * 16 + (lane & 15);
                uint32_t aoff = SWZ((uint32_t)(r * 128 + ks * 32 + (lane >> 4) * 16));
                uint32_t A0, A1, A2, A3;
                LDSM_X4(A0, A1, A2, A3, tb + G3_A + aoff);
#pragma unroll
                for (int nt = 0; nt < 5; nt++)
                    MMAF16(acc[mt][nt], A0, A1, A2, A3, Bf[nt][0], Bf[nt][1]);
            }
        }
        __syncthreads();
    }

#pragma unroll
    for (int mt = 0; mt < 2; mt++)
#pragma unroll
        for (int nt = 0; nt < 5; nt++) {
            int c = wn + nt * 8 + (lane & 3) * 2;
#pragma unroll
            for (int h = 0; h < 2; h++) {
                int row = row0 + wm + mt * 16 + (lane >> 2) + h * 8;
                float v0 = (c < 150) ? fmaxf(acc[mt][nt][h * 2] + ab1[c], 0.f) : 0.f;
                float v1 = (c + 1 < 150) ? fmaxf(acc[mt][nt][h * 2 + 1] + ab1[c + 1], 0.f) : 0.f;
                *(float2*)(H + (long)row * 160 + c) = make_float2(v0, v1);
            }
        }
}

// ======== tok2_tc: attn = relu(h1tok@aW2+ab2).aW3+ab3; we = e*attn ======
// Grid 32. CTA: 64 tokens, K=160, N=160. pair_out-style.
#define PO_A 0
#define PO_B 24576
#define PO_RED 86016
#define PO_SMEM (86016 + 64 * 4 * 4)

__global__ void __launch_bounds__(256, 2) tok2_tc(
    const float* __restrict__ ab2, const float* __restrict__ w3,
    const float* __restrict__ ab3, const float* __restrict__ e)
{
    extern __shared__ __align__(1024) char smem[];
    uint32_t sb = smem_u32(smem);
    float* sRed = (float*)(smem + PO_RED);
    __shared__ float sAttn[64];

    const float* H = g_scratch + OFF_H1TOK;
    float* we = g_scratch + OFF_WE;

    int tid  = threadIdx.x;
    int lane = tid & 31;
    int wid  = tid >> 5;
    int row0 = blockIdx.x * 64;

    int wm = (wid >> 2) * 32;
    int wn = (wid & 3) * 40;

    // stage A: h1tok -> f16
#pragma unroll
    for (int t = 0; t < 8; t++) {
        int idx = tid + t * 256;
        int p = idx >> 5, seg = idx & 31;
        if (seg < 20) {
            const float4* s4 = (const float4*)(H + (long)(row0 + p) * 160 + seg * 8);
            float4 x0 = s4[0], x1 = s4[1];
            uint32_t h01 = pack_h2(x0.x, x0.y), h23 = pack_h2(x0.z, x0.w);
            uint32_t h45 = pack_h2(x1.x, x1.y), h67 = pack_h2(x1.z, x1.w);
            int kblk = seg >> 3, uu = seg & 7;
            uint32_t addr = sb + PO_A + (uint32_t)kblk * 8192
                          + SWZ((uint32_t)(p * 128 + uu * 16));
            STS128(h01, h23, h45, h67, addr);
        }
    }
    // stage B: aW2^T f16
#pragma unroll
    for (int t = 0; t < 15; t++) {
        int idx = tid + t * 256;
        if (idx < 3840) {
            int n = idx / 24, u = idx - n * 24;
            int kblk = u >> 3, uu = u & 7;
            int k0 = kblk * 64 + uu * 8;
            uint4 v = make_uint4(0, 0, 0, 0);
            if (k0 < 160) v = *(const uint4*)(g_aw2t + (long)n * 160 + k0);
            uint32_t addr = sb + PO_B + (uint32_t)kblk * 20480
                          + SWZ((uint32_t)(n * 128 + uu * 16));
            STS128(v.x, v.y, v.z, v.w, addr);
        }
    }
    __syncthreads();

    float acc[2][5][4];
#pragma unroll
    for (int a = 0; a < 2; a++)
#pragma unroll
        for (int b = 0; b < 5; b++)
#pragma unroll
            for (int c = 0; c < 4; c++) acc[a][b][c] = 0.f;

#pragma unroll
    for (int kblk = 0; kblk < 3; kblk++) {
        uint32_t ta = sb + PO_A + (uint32_t)kblk * 8192;
        uint32_t tbb = sb + PO_B + (uint32_t)kblk * 20480;
        int kmax = (kblk == 2) ? 2 : 4;
#pragma unroll
        for (int ks = 0; ks < 4; ks++) {
            if (ks >= kmax) break;
            uint32_t Bf[5][2];
            {
                int m = lane >> 3;
                int n = wn + (m >> 1) * 8 + (lane & 7);
                uint32_t off = SWZ((uint32_t)(n * 128 + ks * 32 + (m & 1) * 16));
                LDSM_X4(Bf[0][0], Bf[0][1], Bf[1][0], Bf[1][1], tbb + off);
            }
            {
                int m = lane >> 3;
                int n = wn + 16 + (m >> 1) * 8 + (lane & 7);
                uint32_t off = SWZ((uint32_t)(n * 128 + ks * 32 + (m & 1) * 16));
                LDSM_X4(Bf[2][0], Bf[2][1], Bf[3][0], Bf[3][1], tbb + off);
            }
            {
                int n = wn + 32 + (lane & 7);
                uint32_t off = SWZ((uint32_t)(n * 128 + ks * 32 + ((lane >> 3) & 1) * 16));
                LDSM_X2(Bf[4][0], Bf[4][1], tbb + off);
            }
#pragma unroll
            for (int mt = 0; mt < 2; mt++) {
                int r = wm + mt * 16 + (lane & 15);
                uint32_t aoff = SWZ((uint32_t)(r * 128 + ks * 32 + (lane >> 4) * 16));
                uint32_t A0, A1, A2, A3;
                LDSM_X4(A0, A1, A2, A3, ta + aoff);
#pragma unroll
                for (int nt = 0; nt < 5; nt++)
                    MMAF16(acc[mt][nt], A0, A1, A2, A3, Bf[nt][0], Bf[nt][1]);
            }
        }
    }

    // epilogue: attn dot
    float part[2][2] = {{0.f, 0.f}, {0.f, 0.f}};
#pragma unroll
    for (int nt = 0; nt < 5; nt++) {
        int c = wn + nt * 8 + (lane & 3) * 2;
        float b0 = 0.f, w0 = 0.f, b1 = 0.f, w1 = 0.f;
        if (c < 150)     { b0 = ab2[c];     w0 = w3[c]; }
        if (c + 1 < 150) { b1 = ab2[c + 1]; w1 = w3[c + 1]; }
#pragma unroll
        for (int mt = 0; mt < 2; mt++)
#pragma unroll
            for (int h = 0; h < 2; h++) {
                part[mt][h] += fmaxf(acc[mt][nt][h * 2] + b0, 0.f) * w0
                             + fmaxf(acc[mt][nt][h * 2 + 1] + b1, 0.f) * w1;
            }
    }
#pragma unroll
    for (int mt = 0; mt < 2; mt++)
#pragma unroll
        for (int h = 0; h < 2; h++) {
            part[mt][h] += __shfl_xor_sync(0xffffffff, part[mt][h], 1);
            part[mt][h] += __shfl_xor_sync(0xffffffff, part[mt][h], 2);
        }
    if ((lane & 3) == 0) {
#pragma unroll
        for (int mt = 0; mt < 2; mt++)
#pragma unroll
            for (int h = 0; h < 2; h++) {
                int row = wm + mt * 16 + (lane >> 2) + h * 8;
                sRed[row * 4 + (wid & 3)] = part[mt][h];
            }
    }
    __syncthreads();
    if (tid < 64) {
        sAttn[tid] = ab3[0] + sRed[tid * 4] + sRed[tid * 4 + 1]
                   + sRed[tid * 4 + 2] + sRed[tid * 4 + 3];
    }
    __syncthreads();

    // we = e * attn (64 tokens x 768)
    for (int it = 0; it < 192; it++) {
        int lin = it * 256 + tid;
        int r = lin / 768, c = lin - r * 768;
        long t = row0 + r;
        we[t * 768 + c] = e[t * 768 + c] * sAttn[r];
    }
}

// ======== gemm3_tc: mh1/hi/hjb raw partials on tensor cores ============
__global__ void __launch_bounds__(256, 2) gemm3_tc()
{
    extern __shared__ __align__(1024) char smem[];
    uint32_t sb = smem_u32(smem);

    const float* g = g_scratch + OFF_G;
    int tid  = threadIdx.x;
    int lane = tid & 31;
    int wid  = tid >> 5;
    int row0 = blockIdx.x * 64;
    int kbase = blockIdx.y * 384;
    int w = blockIdx.z;

    const unsigned short* WT = g_w3t + (long)w * 160 * 2304;
    float* P = g_scratch + OFF_PART + ((long)(w * 6 + blockIdx.y) * 256) * 160;

    int wm = (wid >> 2) * 32;
    int wn = (wid & 3) * 40;

    float acc[2][5][4];
#pragma unroll
    for (int a = 0; a < 2; a++)
#pragma unroll
        for (int b = 0; b < 5; b++)
#pragma unroll
            for (int c = 0; c < 4; c++) acc[a][b][c] = 0.f;

    int arow = tid >> 2;
    int seg  = tid & 3;
    const float* gA = g + (long)(row0 + arow) * 2304 + kbase + seg * 16;

    auto stage = [&](int ch) {
        uint32_t tb = sb + (uint32_t)(ch & 1) * G3_BUF;
        int k0 = ch * 64;
        {
            const float4* s4 = (const float4*)(gA + k0);
            float4 a0 = s4[0], a1 = s4[1], a2 = s4[2], a3 = s4[3];
            uint32_t h0 = pack_h2(a0.x, a0.y), h1 = pack_h2(a0.z, a0.w);
            uint32_t h2 = pack_h2(a1.x, a1.y), h3 = pack_h2(a1.z, a1.w);
            uint32_t h4 = pack_h2(a2.x, a2.y), h5 = pack_h2(a2.z, a2.w);
            uint32_t h6 = pack_h2(a3.x, a3.y), h7 = pack_h2(a3.z, a3.w);
            uint32_t off = (uint32_t)(arow * 128 + seg * 32);
            STS128(h0, h1, h2, h3, tb + G3_A + SWZ(off));
            STS128(h4, h5, h6, h7, tb + G3_A + SWZ(off + 16));
        }
#pragma unroll
        for (int t = 0; t < 5; t++) {
            int idx = tid + t * 256;
            int n = idx >> 3, u = idx & 7;
            uint4 v = *(const uint4*)(WT + (long)n * 2304 + kbase + k0 + u * 8);
            STS128(v.x, v.y, v.z, v.w, tb + G3_B + SWZ((uint32_t)(n * 128 + u * 16)));
        }
    };

    stage(0);
    __syncthreads();

    for (int ch = 0; ch < 6; ch++) {
        if (ch < 5) stage(ch + 1);
        uint32_t tb = sb + (uint32_t)(ch & 1) * G3_BUF;
#pragma unroll
        for (int ks = 0; ks < 4; ks++) {
            uint32_t Bf[5][2];
            {
                int m = lane >> 3;
                int n = wn + (m >> 1) * 8 + (lane & 7);
                uint32_t off = SWZ((uint32_t)(n * 128 + ks * 32 + (m & 1) * 16));
                LDSM_X4(Bf[0][0], Bf[0][1], Bf[1][0], Bf[1][1], tb + G3_B + off);
            }
            {
                int m = lane >> 3;
                int n = wn + 16 + (m >> 1) * 8 + (lane & 7);
                uint32_t off = SWZ((uint32_t)(n * 128 + ks * 32 + (m & 1) * 16));
                LDSM_X4(Bf[2][0], Bf[2][1], Bf[3][0], Bf[3][1], tb + G3_B + off);
            }
            {
                int n = wn + 32 + (lane & 7);
                uint32_t off = SWZ((uint32_t)(n * 128 + ks * 32 + ((lane >> 3) & 1) * 16));
                LDSM_X2(Bf[4][0], Bf[4][1], tb + G3_B + off);
            }
#pragma unroll
            for (int mt = 0; mt < 2; mt++) {
                int r = wm + mt * 16 + (lane & 15);
                uint32_t aoff = SWZ((uint32_t)(r * 128 + ks * 32 + (lane >> 4) * 16));
                uint32_t A0, A1, A2, A3;
                LDSM_X4(A0, A1, A2, A3, tb + G3_A + aoff);
#pragma unroll
                for (int nt = 0; nt < 5; nt++)
                    MMAF16(acc[mt][nt], A0, A1, A2, A3, Bf[nt][0], Bf[nt][1]);
            }
        }
        __syncthreads();
    }

#pragma unroll
    for (int mt = 0; mt < 2; mt++)
#pragma unroll
        for (int nt = 0; nt < 5; nt++) {
            int c = wn + nt * 8 + (lane & 3) * 2;
#pragma unroll
            for (int h = 0; h < 2; h++) {
                int row = row0 + wm + mt * 16 + (lane >> 2) + h * 8;
                *(float2*)(P + (long)row * 160 + c) =
                    make_float2(acc[mt][nt][h * 2], acc[mt][nt][h * 2 + 1]);
            }
        }
}

// ---------------- m tail: m = relu(mh1@mW2+mb2).mW3 + mb3 ---------------
__global__ __launch_bounds__(256) void mtail_kernel(
    const float* __restrict__ W,  const float* __restrict__ b2,
    const float* __restrict__ w3, const float* __restrict__ b3)
{
    const float* A = g_scratch + OFF_MH1;
    float* mo = g_scratch + OFF_M;

    __shared__ float sA[16][20];
    __shared__ float sW[16][160];
    __shared__ float sRed[16][16];

    int tid = threadIdx.x;
    int rg = tid >> 4;
    int cg = tid & 15;
    int row0 = blockIdx.x * 16;

    float acc[10];
#pragma unroll
    for (int b = 0; b < 10; b++) acc[b] = 0.f;

    for (int ch = 0; ch < 10; ch++) {
        int k0 = ch * 16;
        {
            int c = tid & 15, r = tid >> 4;
            float v = 0.f;
            if (k0 + c < 150) v = A[(long)(row0 + r) * 160 + k0 + c];
            sA[c][r] = v;
        }
#pragma unroll
        for (int i = 0; i < 10; i++) {
            int idx = tid + i * 256;
            int k = idx / 160, h = idx - k * 160;
            float v = 0.f;
            if (k0 + k < 150 && h < 150) v = W[(long)(k0 + k) * 150 + h];
            sW[k][h] = v;
        }
        __syncthreads();
#pragma unroll
        for (int k = 0; k < 16; k++) {
            float av = sA[k][rg];
#pragma unroll
            for (int hh = 0; hh < 10; hh += 2) {
                float2 w = *(const float2*)&sW[k][cg * 10 + hh];
                acc[hh]     += av * w.x;
                acc[hh + 1] += av * w.y;
            }
        }
        __syncthreads();
    }

    float partd = 0.f;
#pragma unroll
    for (int hh = 0; hh < 10; hh++) {
        int h = cg * 10 + hh;
        if (h < 150) partd += fmaxf(acc[hh] + b2[h], 0.f) * w3[h];
    }
    sRed[rg][cg] = partd;
    __syncthreads();
    if (tid < 16) {
        float s = b3[0];
#pragma unroll
        for (int c = 0; c < 16; c++) s += sRed[tid][c];
        mo[row0 + tid] = s;
    }
}

// ---------------- 3-way reduce: mh1 / hi / hjb (6 partials) -------------
__global__ __launch_bounds__(160) void reduce_3(
    const float* __restrict__ mb1, const float* __restrict__ pb1)
{
    int row = blockIdx.x, z = blockIdx.y, c = threadIdx.x;
    float s = 0.f;
    if (c < 150) {
#pragma unroll
        for (int k = 0; k < 6; k++)
            s += g_scratch[OFF_PART + ((long)(z * 6 + k) * 256 + row) * 160 + c];
    }
    if (z == 0) {
        float v = (c < 150) ? fmaxf(s + mb1[c], 0.f) : 0.f;
        g_scratch[OFF_MH1 + (long)row * 160 + c] = v;
    } else if (z == 1) {
        g_scratch[OFF_HI + (long)row * 160 + c] = s;
    } else {
        float v = s + ((c < 150) ? pb1[c] : 0.f);
        g_scratch[OFF_HJB + (long)row * 160 + c] = v;
    }
}

// ---------------- g = [e_start | e_end | span_sum], 768 thr/blk ---------
__global__ __launch_bounds__(768) void gather_g_kernel(
    const float* __restrict__ e,
    const int* __restrict__ sp, const int* __restrict__ wd)
{
    const float* we = g_scratch + OFF_WE;
    float* g = g_scratch + OFF_G;
    int s = blockIdx.x, c = threadIdx.x;
    int st = sp[s];
    int en = st + wd[s];
    if (en > TT - 1) en = TT - 1;
    if (en < 0) en = 0;
    g[(long)s * 2304 + c]        = e[(long)st * 768 + c];
    g[(long)s * 2304 + 768 + c]  = e[(long)en * 768 + c];
    float sum = 0.f;
    for (int t = st; t <= en; t++) sum += we[(long)t * 768 + c];
    g[(long)s * 2304 + 1536 + c] = sum;
}

// ================= pair_h1: lower-triangle hij, f16 f32-acc mma =========
#define PH1_A  0
#define PH1_B  32768
#define PH1_BUF 53248
#define PH1_SMEM (2 * PH1_BUF)

__global__ void __launch_bounds__(512, 1) pair_h1_mma()
{
    extern __shared__ __align__(1024) char smem[];
    uint32_t sb = smem_u32(smem);

    const float* g = g_scratch + OFF_G;
    float* h1p     = g_scratch + OFF_H1P;

    int tid  = threadIdx.x;
    int lane = tid & 31;
    int wid  = tid >> 5;
    int jq   = blockIdx.x;
    int ib   = blockIdx.y;

    int j0 = jq * 4;
    int fj = j0 & ~15;
    int i0 = fj + ib * 64;
    if (i0 >= 256) return;
    int M = 256 - i0;
    if (M > 64) M = 64;

    int jsel = wid >> 2;
    int wn   = (wid & 3) * 40;

    float acc[4][5][4];
#pragma unroll
    for (int a = 0; a < 4; a++)
#pragma unroll
        for (int b = 0; b < 5; b++)
#pragma unroll
            for (int c = 0; c < 4; c++) acc[a][b][c] = 0.f;

    int arow = tid >> 3;
    int seg  = tid & 7;
    int gi_row = i0 + arow; if (gi_row > 255) gi_row = 255;
    const float* gi_base = g + (long)gi_row * 2304 + seg * 8;

    auto stage = [&](int ch) {
        uint32_t tb = sb + (uint32_t)(ch & 1) * PH1_BUF;
        int k0 = ch * 64;
        {
            const float4* gi4 = (const float4*)(gi_base + k0);
            float4 a0 = gi4[0], a1 = gi4[1];
            uint32_t sw = SWZ((uint32_t)(arow * 128 + seg * 16));
#pragma unroll
            for (int jj = 0; jj < 4; jj++) {
                const float4* gj4 =
                    (const float4*)(g + (long)(j0 + jj) * 2304 + seg * 8 + k0);
                float4 w0 = gj4[0], w1 = gj4[1];
                uint32_t h01 = pack_h2(a0.x * w0.x, a0.y * w0.y);
                uint32_t h23 = pack_h2(a0.z * w0.z, a0.w * w0.w);
                uint32_t h45 = pack_h2(a1.x * w1.x, a1.y * w1.y);
                uint32_t h67 = pack_h2(a1.z * w1.z, a1.w * w1.w);
                STS128(h01, h23, h45, h67,
                       tb + PH1_A + (uint32_t)jj * 8192 + sw);
            }
        }
#pragma unroll
        for (int t = 0; t < 3; t++) {
            int idx = tid + t * 512;
            if (idx < 1280) {
                int n = idx >> 3, u = idx & 7;
                uint4 v = *(const uint4*)(g_wct + (long)n * 2304 + k0 + u * 8);
                uint32_t sw = SWZ((uint32_t)(n * 128 + u * 16));
                STS128(v.x, v.y, v.z, v.w, tb + PH1_B + sw);
            }
        }
    };

    stage(0);
    __syncthreads();

    for (int ch = 0; ch < 36; ch++) {
        if (ch < 35) stage(ch + 1);
        uint32_t tb = sb + (uint32_t)(ch & 1) * PH1_BUF;
        uint32_t ta = tb + PH1_A + (uint32_t)jsel * 8192;
#pragma unroll
        for (int ks = 0; ks < 4; ks++) {
            uint32_t Bf[5][2];
            {
                int m = lane >> 3;
                int n = wn + (m >> 1) * 8 + (lane & 7);
                uint32_t off = SWZ((uint32_t)(n * 128 + ks * 32 + (m & 1) * 16));
                LDSM_X4(Bf[0][0], Bf[0][1], Bf[1][0], Bf[1][1], tb + PH1_B + off);
            }
            {
                int m = lane >> 3;
                int n = wn + 16 + (m >> 1) * 8 + (lane & 7);
                uint32_t off = SWZ((uint32_t)(n * 128 + ks * 32 + (m & 1) * 16));
                LDSM_X4(Bf[2][0], Bf[2][1], Bf[3][0], Bf[3][1], tb + PH1_B + off);
            }
            {
                int n = wn + 32 + (lane & 7);
                uint32_t off = SWZ((uint32_t)(n * 128 + ks * 32 + ((lane >> 3) & 1) * 16));
                LDSM_X2(Bf[4][0], Bf[4][1], tb + PH1_B + off);
            }
#pragma unroll
            for (int mt = 0; mt < 4; mt++) {
                if (mt * 16 >= M) continue;
                int r = mt * 16 + (lane & 15);
                uint32_t aoff = SWZ((uint32_t)(r * 128 + ks * 32 + (lane >> 4) * 16));
                uint32_t A0, A1, A2, A3;
                LDSM_X4(A0, A1, A2, A3, ta + aoff);
#pragma unroll
                for (int nt = 0; nt < 5; nt++)
                    MMAF16(acc[mt][nt], A0, A1, A2, A3, Bf[nt][0], Bf[nt][1]);
            }
        }
        __syncthreads();
    }

    {
        int j = j0 + jsel;
#pragma unroll
        for (int mt = 0; mt < 4; mt++) {
            if (mt * 16 >= M) continue;
#pragma unroll
            for (int nt = 0; nt < 5; nt++) {
                int c = wn + nt * 8 + (lane & 3) * 2;
#pragma unroll
                for (int h = 0; h < 2; h++) {
                    int i = i0 + mt * 16 + (lane >> 2) + h * 8;
                    *(float2*)(h1p + ((long)i * 256 + j) * 160 + c) =
                        make_float2(acc[mt][nt][h * 2], acc[mt][nt][h * 2 + 1]);
                }
            }
        }
    }
}

// ============ pair_out on tensor cores (64 pairs/CTA, f16) ==============
__global__ void __launch_bounds__(256, 2) pair_out_mma(
    const float* __restrict__ pb2, const float* __restrict__ w3,
    const float* __restrict__ pb3, float* __restrict__ out)
{
    extern __shared__ __align__(1024) char smem[];
    uint32_t sb = smem_u32(smem);
    float* sRed = (float*)(smem + PO_RED);

    const float* h1p = g_scratch + OFF_H1P;
    const float* mm  = g_scratch + OFF_M;
    const float* hi  = g_scratch + OFF_HI;
    const float* hjb = g_scratch + OFF_HJB;

    int tid  = threadIdx.x;
    int lane = tid & 31;
    int wid  = tid >> 5;
    long p0 = (long)blockIdx.x * 64;
    int i_fix = (int)(p0 >> 8);
    int j0 = (int)(p0 & 255);

    int wm = (wid >> 2) * 32;
    int wn = (wid & 3) * 40;

    {
        const float* hirow = hi + (long)i_fix * 160;
#pragma unroll
        for (int t = 0; t < 8; t++) {
            int idx = tid + t * 256;
            int p = idx >> 5, seg = idx & 31;
            if (seg < 20) {
                int j = j0 + p;
                long src = (j <= i_fix) ? ((long)i_fix * 256 + j)
                                        : ((long)j * 256 + i_fix);
                int kc = seg * 8;
                const float4* s4 = (const float4*)(h1p + src * 160 + kc);
                const float4* h4 = (const float4*)(hirow + kc);
                const float4* b4 = (const float4*)(hjb + (long)j * 160 + kc);
                float4 x0 = s4[0], x1 = s4[1];
                float4 y0 = h4[0], y1 = h4[1];
                float4 z0 = b4[0], z1 = b4[1];
                float f0 = fmaxf(x0.x + y0.x + z0.x, 0.f);
                float f1 = fmaxf(x0.y + y0.y + z0.y, 0.f);
                float f2 = fmaxf(x0.z + y0.z + z0.z, 0.f);
                float f3 = fmaxf(x0.w + y0.w + z0.w, 0.f);
                float f4 = fmaxf(x1.x + y1.x + z1.x, 0.f);
                float f5 = fmaxf(x1.y + y1.y + z1.y, 0.f);
                float f6 = fmaxf(x1.z + y1.z + z1.z, 0.f);
                float f7 = fmaxf(x1.w + y1.w + z1.w, 0.f);
                uint32_t h01 = pack_h2(f0, f1), h23 = pack_h2(f2, f3);
                uint32_t h45 = pack_h2(f4, f5), h67 = pack_h2(f6, f7);
                int kblk = seg >> 3, uu = seg & 7;
                uint32_t addr = sb + PO_A + (uint32_t)kblk * 8192
                              + SWZ((uint32_t)(p * 128 + uu * 16));
                STS128(h01, h23, h45, h67, addr);
            }
        }
    }
    {
#pragma unroll
        for (int t = 0; t < 15; t++) {
            int idx = tid + t * 256;
            if (idx < 3840) {
                int n = idx / 24, u = idx - n * 24;
                int kblk = u >> 3, uu = u & 7;
                int k0 = kblk * 64 + uu * 8;
                uint4 v = make_uint4(0, 0, 0, 0);
                if (k0 < 160) v = *(const uint4*)(g_w2t + (long)n * 160 + k0);
                uint32_t addr = sb + PO_B + (uint32_t)kblk * 20480
                              + SWZ((uint32_t)(n * 128 + uu * 16));
                STS128(v.x, v.y, v.z, v.w, addr);
            }
        }
    }
    __syncthreads();

    float acc[2][5][4];
#pragma unroll
    for (int a = 0; a < 2; a++)
#pragma unroll
        for (int b = 0; b < 5; b++)
#pragma unroll
            for (int c = 0; c < 4; c++) acc[a][b][c] = 0.f;

#pragma unroll
    for (int kblk = 0; kblk < 3; kblk++) {
        uint32_t ta = sb + PO_A + (uint32_t)kblk * 8192;
        uint32_t tbb = sb + PO_B + (uint32_t)kblk * 20480;
        int kmax = (kblk == 2) ? 2 : 4;
#pragma unroll
        for (int ks = 0; ks < 4; ks++) {
            if (ks >= kmax) break;
            uint32_t Bf[5][2];
            {
                int m = lane >> 3;
                int n = wn + (m >> 1) * 8 + (lane & 7);
                uint32_t off = SWZ((uint32_t)(n * 128 + ks * 32 + (m & 1) * 16));
                LDSM_X4(Bf[0][0], Bf[0][1], Bf[1][0], Bf[1][1], tbb + off);
            }
            {
                int m = lane >> 3;
                int n = wn + 16 + (m >> 1) * 8 + (lane & 7);
                uint32_t off = SWZ((uint32_t)(n * 128 + ks * 32 + (m & 1) * 16));
                LDSM_X4(Bf[2][0], Bf[2][1], Bf[3][0], Bf[3][1], tbb + off);
            }
            {
                int n = wn + 32 + (lane & 7);
                uint32_t off = SWZ((uint32_t)(n * 128 + ks * 32 + ((lane >> 3) & 1) * 16));
                LDSM_X2(Bf[4][0], Bf[4][1], tbb + off);
            }
#pragma unroll
            for (int mt = 0; mt < 2; mt++) {
                int r = wm + mt * 16 + (lane & 15);
                uint32_t aoff = SWZ((uint32_t)(r * 128 + ks * 32 + (lane >> 4) * 16));
                uint32_t A0, A1, A2, A3;
                LDSM_X4(A0, A1, A2, A3, ta + aoff);
#pragma unroll
                for (int nt = 0; nt < 5; nt++)
                    MMAF16(acc[mt][nt], A0, A1, A2, A3, Bf[nt][0], Bf[nt][1]);
            }
        }
    }

    float part[2][2] = {{0.f, 0.f}, {0.f, 0.f}};
#pragma unroll
    for (int nt = 0; nt < 5; nt++) {
        int c = wn + nt * 8 + (lane & 3) * 2;
        float b0 = 0.f, w0 = 0.f, b1 = 0.f, w1 = 0.f;
        if (c < 150)     { b0 = pb2[c];     w0 = w3[c]; }
        if (c + 1 < 150) { b1 = pb2[c + 1]; w1 = w3[c + 1]; }
#pragma unroll
        for (int mt = 0; mt < 2; mt++)
#pragma unroll
            for (int h = 0; h < 2; h++) {
                part[mt][h] += fmaxf(acc[mt][nt][h * 2] + b0, 0.f) * w0
                             + fmaxf(acc[mt][nt][h * 2 + 1] + b1, 0.f) * w1;
            }
    }
#pragma unroll
    for (int mt = 0; mt < 2; mt++)
#pragma unroll
        for (int h = 0; h < 2; h++) {
            part[mt][h] += __shfl_xor_sync(0xffffffff, part[mt][h], 1);
            part[mt][h] += __shfl_xor_sync(0xffffffff, part[mt][h], 2);
        }
    if ((lane & 3) == 0) {
#pragma unroll
        for (int mt = 0; mt < 2; mt++)
#pragma unroll
            for (int h = 0; h < 2; h++) {
                int row = wm + mt * 16 + (lane >> 2) + h * 8;
                sRed[row * 4 + (wid & 3)] = part[mt][h];
            }
    }
    __syncthreads();
    if (tid < 64) {
        float s = pb3[0] + sRed[tid * 4] + sRed[tid * 4 + 1]
                + sRed[tid * 4 + 2] + sRed[tid * 4 + 3];
        long pr = p0 + tid;
        int jj = (int)(pr & 255);
        float v = (mm[i_fix] + mm[jj] + s) * (1.f / 3.f);
        v = fminf(fmaxf(v, 0.f), 1.f);
        out[pr] = v;
    }
}

// ---------------- launch ------------------------------------------------
extern "C" void kernel_launch(void* const* d_in, const int* in_sizes, int n_in,
                              void* d_out, int out_size)
{
    const float* e   = (const float*)d_in[0];
    const int*   sp  = (const int*)d_in[1];
    const int*   wd  = (const int*)d_in[2];
    const float* aW1 = (const float*)d_in[3];
    const float* ab1 = (const float*)d_in[4];
    const float* aW2 = (const float*)d_in[5];
    const float* ab2 = (const float*)d_in[6];
    const float* aW3 = (const float*)d_in[7];
    const float* ab3 = (const float*)d_in[8];
    const float* mW1 = (const float*)d_in[9];
    const float* mb1 = (const float*)d_in[10];
    const float* mW2 = (const float*)d_in[11];
    const float* mb2 = (const float*)d_in[12];
    const float* mW3 = (const float*)d_in[13];
    const float* mb3 = (const float*)d_in[14];
    const float* pW1 = (const float*)d_in[15];
    const float* pb1 = (const float*)d_in[16];
    const float* pW2 = (const float*)d_in[17];
    const float* pb2 = (const float*)d_in[18];
    const float* pW3 = (const float*)d_in[19];
    const float* pb3 = (const float*)d_in[20];
    float* out = (float*)d_out;

    cudaFuncSetAttribute(pair_h1_mma, cudaFuncAttributeMaxDynamicSharedMemorySize,
                         PH1_SMEM);
    cudaFuncSetAttribute(pair_out_mma, cudaFuncAttributeMaxDynamicSharedMemorySize,
                         PO_SMEM);
    cudaFuncSetAttribute(gemm3_tc, cudaFuncAttributeMaxDynamicSharedMemorySize,
                         G3_SMEM);
    cudaFuncSetAttribute(tok1_tc, cudaFuncAttributeMaxDynamicSharedMemorySize,
                         G3_SMEM);
    cudaFuncSetAttribute(tok2_tc, cudaFuncAttributeMaxDynamicSharedMemorySize,
                         PO_SMEM);

    // weight preps (independent)
    prep_weights<<<1440, 256>>>(pW1 + 4608L * 150, pW2);
    prep_w3<<<4320, 256>>>(mW1, pW1, pW1 + 2304L * 150);
    prep_w12<<<480, 256>>>(aW1, aW2);

    // token path on tensor cores
    tok1_tc<<<32, 256, G3_SMEM>>>(e, ab1);
    tok2_tc<<<32, 256, PO_SMEM>>>(ab2, aW3, ab3, e);

    // span features
    gather_g_kernel<<<256, 768>>>(e, sp, wd);

    // mh1 / hi / hjb on tensor cores: split-K (6 x 384) x 3 weights
    gemm3_tc<<<dim3(4, 6, 3), 256, G3_SMEM>>>();
    reduce_3<<<dim3(256, 3), 160>>>(mb1, pb1);

    // lower-triangle hij on tensor cores (f32-acc, 4 j's per CTA)
    pair_h1_mma<<<dim3(64, 4), 512, PH1_SMEM>>>();

    // m tail (fused layer2 + dot)
    mtail_kernel<<<16, 256>>>(mW2, mb2, mW3, mb3);

    // pairwise output on tensor cores
    pair_out_mma<<<1024, 256, PO_SMEM>>>(pb2, pW3, pb3, out);
}